// round 14
// baseline (speedup 1.0000x reference)
#include <cuda_runtime.h>
#include <cuda_bf16.h>
#include <math.h>

#define BG   128
#define NPG  256
#define EPG  2048
#define EMB  256
#define NL   5
#define NTOT (BG*NPG)
#define ETOT (BG*EPG)

typedef unsigned long long ull;
typedef __nv_bfloat16 bf16;

// ------------------------------ scratch -------------------------------------
__device__ unsigned g_pk[(size_t)BG*NPG*NPG];   // zero at entry; self-restoring
__device__ float g_cs [BG*NPG];
__device__ float g_rs [BG*NPG];
__device__ float g_h  [NTOT*EMB];
__device__ float g_hin[NTOT*EMB];
__device__ float g_t  [NTOT*2*EMB];
__device__ float g_h2 [NTOT*EMB];
__device__ float g_vn [BG*EMB];
__device__ float g_ewt[16];
__device__ int   g_deg[NTOT];
__device__ int   g_ptr[NTOT];
__device__ int   g_cur[NTOT];
__device__ int   g_csrc[ETOT];
__device__ int   g_cea [ETOT];
__device__ float g_sum[NL*2*512];
__device__ float g_sq [NL*2*512];

__device__ __align__(16) bf16 g_Ahp[(size_t)BG*NPG*NPG], g_Alp[(size_t)BG*NPG*NPG];
__device__ __align__(16) bf16 g_x1h[NTOT*EMB], g_x1l[NTOT*EMB];
__device__ __align__(16) bf16 g_x2h[NTOT*EMB], g_x2l[NTOT*EMB];
__device__ __align__(16) bf16 g_zh [NTOT*EMB], g_zl [NTOT*EMB];
__device__ __align__(16) bf16 g_th [NTOT*2*EMB], g_tl [NTOT*2*EMB];
__device__ __align__(16) bf16 g_w1h[NL*EMB*2*EMB],  g_w1l[NL*EMB*2*EMB];
__device__ __align__(16) bf16 g_w2h[NL*2*EMB*EMB],  g_w2l[NL*2*EMB*EMB];

__device__ __forceinline__ void splitw(float v, bf16* __restrict__ h,
                                       bf16* __restrict__ l, size_t i) {
    bf16 hv = __float2bfloat16(v);
    h[i] = hv;
    l[i] = __float2bfloat16(v - __bfloat162float(hv));
}

// ------------------------------ setup kernels -------------------------------
__global__ void k_zero() {
    int i = blockIdx.x * 256 + threadIdx.x;
    if (i < NTOT) g_deg[i] = 0;
    if (i < NL*2*512) { g_sum[i] = 0.f; g_sq[i] = 0.f; }
}

__global__ void k_ewt(const float* __restrict__ bh, const float* __restrict__ w,
                      const float* __restrict__ b) {
    int warp = threadIdx.x >> 5, lane = threadIdx.x & 31;
    if (warp < 16) {
        float v = bh[warp*64 + lane] * w[lane] + bh[warp*64 + 32 + lane] * w[32 + lane];
        #pragma unroll
        for (int o = 16; o; o >>= 1) v += __shfl_down_sync(0xffffffffu, v, o);
        if (lane == 0) g_ewt[warp] = 1.f / (1.f + expf(-(v + b[0])));
    }
}

__global__ void k_scatter(const int* __restrict__ lei, const int* __restrict__ eai) {
    int idx = blockIdx.x * 256 + threadIdx.x;
    if (idx >= ETOT) return;
    int b = idx / EPG, k = idx - b * EPG;
    int s = lei[(size_t)b*2*EPG + k];
    int d = lei[(size_t)b*2*EPG + EPG + k];
    int t = eai[idx];
    unsigned key = ((unsigned)(k + 1) << 4) | (unsigned)t;
    atomicMax(&g_pk[(size_t)b*NPG*NPG + (size_t)s*NPG + d], key);
    atomicAdd(&g_deg[b*NPG + d], 1);
}

__global__ void k_adjprep() {
    int g = blockIdx.x;
    int tid = threadIdx.x, lane = tid & 31, warp = tid >> 5;
    __shared__ float s_cs[NPG], s_rs[NPG];
    for (int i = tid; i < NPG; i += 256) s_cs[i] = 0.f;
    __syncthreads();
    const unsigned* P = g_pk + (size_t)g*NPG*NPG;
    float csl[8] = {};
    for (int rb = 0; rb < NPG; rb += 8) {
        int r = rb + warp;
        float rsum = 0.f;
        #pragma unroll
        for (int k = 0; k < 8; k++) {
            int c = lane + k*32;
            unsigned p = P[(size_t)r*NPG + c];
            float v = p ? g_ewt[p & 15u] : 0.f;
            if (r == c) v += 1.f;
            rsum += v;
            csl[k] += v;
        }
        #pragma unroll
        for (int o = 16; o; o >>= 1) rsum += __shfl_down_sync(0xffffffffu, rsum, o);
        if (lane == 0) s_rs[r] = rsqrtf(rsum);
    }
    #pragma unroll
    for (int k = 0; k < 8; k++) atomicAdd(&s_cs[lane + k*32], csl[k]);
    __syncthreads();
    for (int i = tid; i < NPG; i += 256) {
        g_cs[g*NPG + i] = rsqrtf(s_cs[i]);
        g_rs[g*NPG + i] = s_rs[i];
    }
}

__global__ void k_adjnorm() {
    size_t idx = (size_t)blockIdx.x * 256 + threadIdx.x;
    int g = (int)(idx >> 16);
    int r = (int)((idx >> 8) & 255);
    int c = (int)(idx & 255);
    unsigned p = g_pk[idx];
    float v = p ? g_ewt[p & 15u] : 0.f;
    if (p) g_pk[idx] = 0u;
    if (r == c) v += 1.f;
    v *= g_cs[g*NPG + r] * g_rs[g*NPG + c];
    splitw(v, g_Ahp, g_Alp, idx);
}

__global__ void k_scan() {
    int g = blockIdx.x, tid = threadIdx.x;
    __shared__ int s[NPG];
    int d = g_deg[g*NPG + tid];
    s[tid] = d;
    __syncthreads();
    for (int off = 1; off < NPG; off <<= 1) {
        int v = (tid >= off) ? s[tid - off] : 0;
        __syncthreads();
        s[tid] += v;
        __syncthreads();
    }
    int excl = s[tid] - d;
    g_ptr[g*NPG + tid] = g*EPG + excl;
    g_cur[g*NPG + tid] = g*EPG + excl;
}

__global__ void k_csrfill(const int* __restrict__ lei, const int* __restrict__ eai) {
    int idx = blockIdx.x * 256 + threadIdx.x;
    if (idx >= ETOT) return;
    int b = idx / EPG, k = idx - b * EPG;
    int s = lei[(size_t)b*2*EPG + k];
    int d = lei[(size_t)b*2*EPG + EPG + k];
    int pos = atomicAdd(&g_cur[b*NPG + d], 1);
    g_csrc[pos] = b*NPG + s;
    g_cea [pos] = eai[idx];
}

__global__ void k_gather(const int* __restrict__ aidx, const float* __restrict__ aemb) {
    int idx = blockIdx.x * 256 + threadIdx.x;
    int n = idx >> 8, c = idx & 255;
    float v = aemb[aidx[n]*EMB + c];
    g_h[idx] = v;
    splitw(v, g_x1h, g_x1l, idx);
}

__global__ void k_split(const float* __restrict__ w, bf16* __restrict__ h,
                        bf16* __restrict__ l, int n) {
    int i = blockIdx.x * 256 + threadIdx.x;
    if (i < n) splitw(w[i], h, l, i);
}

// ------------------------------ pipelined bf16x3 tensor GEMM ----------------
// mode 0: Cf = acc + bias            (MLP GEMMs)
// mode 2: Chi/Clo = split(acc), Y += acc   (propagation)
#define BM 128
#define BN 64
#define APAD 40
#define BPAD 72
#define ASEG (128*APAD)
#define BSEG (32*BPAD)
#define BBASE (6*ASEG)
#define SMEM_BYTES ((6*ASEG + 6*BSEG)*2)

__device__ __forceinline__ void cpa16(unsigned s, const void* g) {
    asm volatile("cp.async.cg.shared.global [%0], [%1], 16;" :: "r"(s), "l"(g));
}
#define LDSM4(r0,r1,r2,r3,a)                                                   \
    asm volatile("ldmatrix.sync.aligned.m8n8.x4.shared.b16 {%0,%1,%2,%3}, [%4];" \
        : "=r"(r0),"=r"(r1),"=r"(r2),"=r"(r3) : "r"(a))
#define LDSM4T(r0,r1,r2,r3,a)                                                  \
    asm volatile("ldmatrix.sync.aligned.m8n8.x4.trans.shared.b16 {%0,%1,%2,%3}, [%4];" \
        : "=r"(r0),"=r"(r1),"=r"(r2),"=r"(r3) : "r"(a))
#define MMA_BF16(c, a, b)                                                     \
    asm volatile(                                                             \
        "mma.sync.aligned.m16n8k16.row.col.f32.bf16.bf16.f32 "                \
        "{%0,%1,%2,%3}, {%4,%5,%6,%7}, {%8,%9}, {%0,%1,%2,%3};\n"             \
        : "+f"((c)[0]), "+f"((c)[1]), "+f"((c)[2]), "+f"((c)[3])              \
        : "r"((a)[0]), "r"((a)[1]), "r"((a)[2]), "r"((a)[3]),                 \
          "r"((b)[0]), "r"((b)[1]))

__global__ void __launch_bounds__(256, 2)
k_mma(const bf16* __restrict__ Ah, const bf16* __restrict__ Al,
      const bf16* __restrict__ Bh, const bf16* __restrict__ Bl,
      const float* __restrict__ bias,
      float* __restrict__ Cf, bf16* __restrict__ Chi, bf16* __restrict__ Clo,
      float* __restrict__ Y, int relu,
      int M, int N, int K, long sA, long sB, long sC) {
    extern __shared__ bf16 smbuf[];
    Ah += (size_t)blockIdx.z * sA;  Al += (size_t)blockIdx.z * sA;
    Bh += (size_t)blockIdx.z * sB;  Bl += (size_t)blockIdx.z * sB;
    if (Cf)  Cf  += (size_t)blockIdx.z * sC;
    if (Chi) { Chi += (size_t)blockIdx.z * sC; Clo += (size_t)blockIdx.z * sC; }
    if (Y)   Y   += (size_t)blockIdx.z * sC;

    unsigned sb = (unsigned)__cvta_generic_to_shared(smbuf);
    int tid = threadIdx.x, lane = tid & 31, warp = tid >> 5;
    int wm = warp >> 1, wn = warp & 1;
    int bm = blockIdx.y * BM, bn = blockIdx.x * BN;

    int ar = tid >> 2, ac = (tid & 3) * 8;
    int br = tid >> 3, bc = (tid & 7) * 8;
    int lr = lane & 15, lc = (lane >> 4) * 8;

    float acc[2][4][4];
    #pragma unroll
    for (int i = 0; i < 2; i++)
        #pragma unroll
        for (int j = 0; j < 4; j++)
            #pragma unroll
            for (int r = 0; r < 4; r++) acc[i][j][r] = 0.f;

    int niter = K / 32;

#define ISSUE(buf, kk) {                                                         \
    unsigned a0 = sb + (unsigned)(((buf)*2+0)*ASEG)*2;                            \
    unsigned a1 = sb + (unsigned)(((buf)*2+1)*ASEG)*2;                            \
    unsigned b0 = sb + (unsigned)((BBASE + ((buf)*2+0)*BSEG))*2;                  \
    unsigned b1 = sb + (unsigned)((BBASE + ((buf)*2+1)*BSEG))*2;                  \
    cpa16(a0 + (ar*APAD + ac)*2,      Ah + (size_t)(bm + ar)*K + (kk) + ac);      \
    cpa16(a0 + ((ar+64)*APAD + ac)*2, Ah + (size_t)(bm + ar + 64)*K + (kk) + ac); \
    cpa16(a1 + (ar*APAD + ac)*2,      Al + (size_t)(bm + ar)*K + (kk) + ac);      \
    cpa16(a1 + ((ar+64)*APAD + ac)*2, Al + (size_t)(bm + ar + 64)*K + (kk) + ac); \
    cpa16(b0 + (br*BPAD + bc)*2,      Bh + (size_t)((kk) + br)*N + bn + bc);      \
    cpa16(b1 + (br*BPAD + bc)*2,      Bl + (size_t)((kk) + br)*N + bn + bc);      \
}

    ISSUE(0, 0);
    asm volatile("cp.async.commit_group;");
    ISSUE(1, 32);
    asm volatile("cp.async.commit_group;");

    int cbuf = 0, ibuf = 2;
    for (int it = 0; it < niter; it++) {
        asm volatile("cp.async.wait_group 1;");
        __syncthreads();
        if (it + 2 < niter) { int kk = (it + 2) * 32; ISSUE(ibuf, kk); }
        asm volatile("cp.async.commit_group;");

        unsigned aH = sb + (unsigned)((cbuf*2+0)*ASEG)*2;
        unsigned aL = sb + (unsigned)((cbuf*2+1)*ASEG)*2;
        unsigned bH = sb + (unsigned)((BBASE + (cbuf*2+0)*BSEG))*2;
        unsigned bL = sb + (unsigned)((BBASE + (cbuf*2+1)*BSEG))*2;

        #pragma unroll
        for (int ks = 0; ks < 2; ks++) {
            unsigned ah[2][4], al[2][4], bh[4][2], bl[4][2];
            #pragma unroll
            for (int mf = 0; mf < 2; mf++) {
                unsigned off = (unsigned)(((wm*32 + mf*16 + lr)*APAD + ks*16 + lc)*2);
                LDSM4(ah[mf][0], ah[mf][1], ah[mf][2], ah[mf][3], aH + off);
                LDSM4(al[mf][0], al[mf][1], al[mf][2], al[mf][3], aL + off);
            }
            #pragma unroll
            for (int p = 0; p < 2; p++) {
                unsigned off = (unsigned)(((ks*16 + lr)*BPAD + wn*32 + p*16 + lc)*2);
                unsigned r0, r1, r2, r3;
                LDSM4T(r0, r1, r2, r3, bH + off);
                bh[2*p][0] = r0; bh[2*p][1] = r1; bh[2*p+1][0] = r2; bh[2*p+1][1] = r3;
                LDSM4T(r0, r1, r2, r3, bL + off);
                bl[2*p][0] = r0; bl[2*p][1] = r1; bl[2*p+1][0] = r2; bl[2*p+1][1] = r3;
            }
            #pragma unroll
            for (int mf = 0; mf < 2; mf++)
                #pragma unroll
                for (int nf = 0; nf < 4; nf++) {
                    float* c = acc[mf][nf];
                    MMA_BF16(c, ah[mf], bl[nf]);
                    MMA_BF16(c, al[mf], bh[nf]);
                    MMA_BF16(c, ah[mf], bh[nf]);
                }
        }
        cbuf = (cbuf == 2) ? 0 : cbuf + 1;
        ibuf = (ibuf == 2) ? 0 : ibuf + 1;
    }

    int gid = lane >> 2, tig = lane & 3;
    #pragma unroll
    for (int mf = 0; mf < 2; mf++) {
        #pragma unroll
        for (int nf = 0; nf < 4; nf++) {
            int r0 = bm + wm*32 + mf*16 + gid;
            int c0 = bn + wn*32 + nf*8 + 2*tig;
            float b0 = 0.f, b1 = 0.f;
            if (bias) { b0 = bias[c0]; b1 = bias[c0+1]; }
            float* c = acc[mf][nf];
            #pragma unroll
            for (int half = 0; half < 2; half++) {
                int r = r0 + half*8;
                float v0 = c[half*2+0] + b0, v1 = c[half*2+1] + b1;
                if (relu) { v0 = fmaxf(v0, 0.f); v1 = fmaxf(v1, 0.f); }
                if (Cf)
                    *reinterpret_cast<float2*>(Cf + (size_t)r*N + c0) = make_float2(v0, v1);
                if (Chi) {
                    bf16 h0 = __float2bfloat16(v0), h1 = __float2bfloat16(v1);
                    *reinterpret_cast<__nv_bfloat162*>(Chi + (size_t)r*N + c0) =
                        __halves2bfloat162(h0, h1);
                    bf16 l0 = __float2bfloat16(v0 - __bfloat162float(h0));
                    bf16 l1 = __float2bfloat16(v1 - __bfloat162float(h1));
                    *reinterpret_cast<__nv_bfloat162*>(Clo + (size_t)r*N + c0) =
                        __halves2bfloat162(l0, l1);
                }
                if (Y) {
                    float2* y = reinterpret_cast<float2*>(Y + (size_t)r*N + c0);
                    float2 yo = *y;
                    yo.x += v0; yo.y += v1;
                    *y = yo;
                }
            }
        }
    }
#undef ISSUE
}

// ------------------------------ fused GIN aggregate --------------------------
__global__ void k_agg(const float* __restrict__ eembL, const float* __restrict__ epsp,
                      const float* __restrict__ vnp, int vnstride, float hscale) {
    int n = blockIdx.x, c = threadIdx.x;
    int b = n >> 8;
    float vnv = vnp[b*vnstride + c];
    int start = g_ptr[n], deg = g_deg[n];
    float own = g_h[(size_t)n*EMB + c] * hscale + vnv;
    g_hin[(size_t)n*EMB + c] = own;
    float val = 0.f;
    for (int k = 0; k < deg; k++) {
        int s = g_csrc[start + k];
        int t = g_cea [start + k];
        float m = g_h[(size_t)s*EMB + c] * hscale + vnv + eembL[t*EMB + c];
        val += fmaxf(m, 0.f);
    }
    float z = (1.f + *epsp) * own + val;
    splitw(z, g_zh, g_zl, (size_t)n*EMB + c);
}

// ------------------------------ batchnorm -----------------------------------
__global__ void k_bnstats(const float* __restrict__ X, int C,
                          float* __restrict__ sum, float* __restrict__ sq) {
    int r0 = blockIdx.x * 128;
    for (int c = threadIdx.x; c < C; c += 256) {
        float s = 0.f, q = 0.f;
        for (int r = 0; r < 128; r++) {
            float v = X[(size_t)(r0 + r)*C + c];
            s += v; q += v * v;
        }
        atomicAdd(&sum[c], s);
        atomicAdd(&sq[c], q);
    }
}

__device__ __forceinline__ void bn_coef(const float* __restrict__ sum,
                                        const float* __restrict__ sq,
                                        const float* __restrict__ gamma,
                                        const float* __restrict__ beta,
                                        int c, float& sc, float& sh) {
    float mu  = sum[c] * (1.f / NTOT);
    float var = sq[c] * (1.f / NTOT) - mu * mu;
    sc = gamma[c] * rsqrtf(var + 1e-5f);
    sh = beta[c] - mu * sc;
}

__global__ void k_bnapplyS(const float* __restrict__ X,
                           const float* __restrict__ gamma, const float* __restrict__ beta,
                           const float* __restrict__ sum, const float* __restrict__ sq) {
    int idx = blockIdx.x * 256 + threadIdx.x;
    int c = idx & (2*EMB - 1);
    float sc, sh;
    bn_coef(sum, sq, gamma, beta, c, sc, sh);
    float v = fmaxf(X[idx] * sc + sh, 0.f);
    splitw(v, g_th, g_tl, idx);
}

__global__ void k_bnapply(const float* __restrict__ X, float* __restrict__ O,
                          const float* __restrict__ gamma, const float* __restrict__ beta,
                          const float* __restrict__ sum, const float* __restrict__ sq,
                          int act) {
    int idx = blockIdx.x * 256 + threadIdx.x;
    int c = idx & 255;
    float sc, sh;
    bn_coef(sum, sq, gamma, beta, c, sc, sh);
    float v = X[idx] * sc + sh;
    if (act) v = fmaxf(v, 0.f);
    O[idx] = v;
}

// ------------------------------ fused virtual-node MLP ----------------------
// vt = colsum(hin) + vn_prev; vn = relu(relu(vt@w1+b1)@w2+b2). Exact fp32.
__global__ void __launch_bounds__(256)
k_vnmlp(const float* __restrict__ w1, const float* __restrict__ b1,
        const float* __restrict__ w2, const float* __restrict__ b2,
        const float* __restrict__ vnp, int vnstride) {
    __shared__ float s_vt[EMB];
    __shared__ float s_y1[2*EMB];
    int b = blockIdx.x, tid = threadIdx.x;

    const float* base = g_hin + (size_t)b*NPG*EMB + tid;
    float s = 0.f;
    #pragma unroll 4
    for (int r = 0; r < NPG; r++) s += base[(size_t)r*EMB];
    s_vt[tid] = s + vnp[b*vnstride + tid];
    __syncthreads();

    float a0 = b1[tid], a1 = b1[tid + 256];
    #pragma unroll 4
    for (int k = 0; k < EMB; k++) {
        float v = s_vt[k];
        a0 = fmaf(v, w1[(size_t)k*512 + tid],       a0);
        a1 = fmaf(v, w1[(size_t)k*512 + tid + 256], a1);
    }
    s_y1[tid]       = fmaxf(a0, 0.f);
    s_y1[tid + 256] = fmaxf(a1, 0.f);
    __syncthreads();

    float a = b2[tid];
    #pragma unroll 4
    for (int j = 0; j < 2*EMB; j++)
        a = fmaf(s_y1[j], w2[(size_t)j*256 + tid], a);
    g_vn[b*EMB + tid] = fmaxf(a, 0.f);
}

// ------------------------------ host orchestration --------------------------
extern "C" void kernel_launch(void* const* d_in, const int* in_sizes, int n_in,
                              void* d_out, int out_size) {
    const int ab = n_in - 19;
    const int*   atom_idx = (const int*)  d_in[0];
    const int*   lei      = (const int*)  d_in[1];
    const int*   eai      = (const int*)  d_in[2];
    const float* atom_emb = (const float*)d_in[ab + 0];
    const float* bemb_h   = (const float*)d_in[ab + 1];
    const float* elin_w   = (const float*)d_in[ab + 2];
    const float* elin_b   = (const float*)d_in[ab + 3];
    const float* bemb_l   = (const float*)d_in[ab + 4];
    const float* gin_eps  = (const float*)d_in[ab + 5];
    const float* mlp_w1   = (const float*)d_in[ab + 6];
    const float* mlp_b1   = (const float*)d_in[ab + 7];
    const float* bn_g     = (const float*)d_in[ab + 8];
    const float* bn_b     = (const float*)d_in[ab + 9];
    const float* mlp_w2   = (const float*)d_in[ab + 10];
    const float* mlp_b2   = (const float*)d_in[ab + 11];
    const float* obn_g    = (const float*)d_in[ab + 12];
    const float* obn_b    = (const float*)d_in[ab + 13];
    const float* vn_emb   = (const float*)d_in[ab + 14];
    const float* vn_w1    = (const float*)d_in[ab + 15];
    const float* vn_b1    = (const float*)d_in[ab + 16];
    const float* vn_w2    = (const float*)d_in[ab + 17];
    const float* vn_b2    = (const float*)d_in[ab + 18];
    float* out = (float*)d_out;

    static int smem_set = 0;
    if (!smem_set) {
        cudaFuncSetAttribute(k_mma, cudaFuncAttributeMaxDynamicSharedMemorySize, SMEM_BYTES);
        smem_set = 1;
    }

    float *p_t, *p_h2, *p_h, *p_vn, *p_sum, *p_sq;
    cudaGetSymbolAddress((void**)&p_t,  g_t);
    cudaGetSymbolAddress((void**)&p_h2, g_h2);
    cudaGetSymbolAddress((void**)&p_h,  g_h);
    cudaGetSymbolAddress((void**)&p_vn, g_vn);
    cudaGetSymbolAddress((void**)&p_sum, g_sum);
    cudaGetSymbolAddress((void**)&p_sq,  g_sq);
    bf16 *pAh, *pAl, *px1h, *px1l, *px2h, *px2l, *pzh, *pzl, *pth, *ptl;
    bf16 *pw1h, *pw1l, *pw2h, *pw2l;
    cudaGetSymbolAddress((void**)&pAh,  g_Ahp);
    cudaGetSymbolAddress((void**)&pAl,  g_Alp);
    cudaGetSymbolAddress((void**)&px1h, g_x1h);
    cudaGetSymbolAddress((void**)&px1l, g_x1l);
    cudaGetSymbolAddress((void**)&px2h, g_x2h);
    cudaGetSymbolAddress((void**)&px2l, g_x2l);
    cudaGetSymbolAddress((void**)&pzh,  g_zh);
    cudaGetSymbolAddress((void**)&pzl,  g_zl);
    cudaGetSymbolAddress((void**)&pth,  g_th);
    cudaGetSymbolAddress((void**)&ptl,  g_tl);
    cudaGetSymbolAddress((void**)&pw1h, g_w1h);
    cudaGetSymbolAddress((void**)&pw1l, g_w1l);
    cudaGetSymbolAddress((void**)&pw2h, g_w2h);
    cudaGetSymbolAddress((void**)&pw2l, g_w2l);

    const int NE = NTOT*EMB/256;
    const int W  = EMB*2*EMB;

    // ---- setup ----
    k_zero<<<NTOT/256, 256>>>();
    k_ewt<<<1, 512>>>(bemb_h, elin_w, elin_b);
    k_scatter<<<ETOT/256, 256>>>(lei, eai);
    k_adjprep<<<BG, 256>>>();
    k_adjnorm<<<(int)((size_t)BG*NPG*NPG/256), 256>>>();
    k_scan<<<BG, 256>>>();
    k_csrfill<<<ETOT/256, 256>>>(lei, eai);
    k_gather<<<NE, 256>>>(atom_idx, atom_emb);
    k_split<<<NL*W/256, 256>>>(mlp_w1, pw1h, pw1l, NL*W);
    k_split<<<NL*W/256, 256>>>(mlp_w2, pw2h, pw2l, NL*W);

    // ---- propagation: g_h accumulates f + Af + A^2 f + A^3 f ----
    dim3 pg(EMB/BN, NPG/BM, BG);
    long sAdj = (long)NPG*NPG, sX = (long)NPG*EMB;
    k_mma<<<pg, 256, SMEM_BYTES>>>(pAh, pAl, px1h, px1l, nullptr,
                                   nullptr, px2h, px2l, p_h, 0, NPG, EMB, NPG, sAdj, sX, sX);
    k_mma<<<pg, 256, SMEM_BYTES>>>(pAh, pAl, px2h, px2l, nullptr,
                                   nullptr, px1h, px1l, p_h, 0, NPG, EMB, NPG, sAdj, sX, sX);
    k_mma<<<pg, 256, SMEM_BYTES>>>(pAh, pAl, px1h, px1l, nullptr,
                                   nullptr, px2h, px2l, p_h, 0, NPG, EMB, NPG, sAdj, sX, sX);

    // ---- GIN + virtual-node stack ----
    const float* vnp = vn_emb;
    int vnstride = 0;

    for (int l = 0; l < NL; l++) {
        float hscale = (l == 0) ? 0.25f : 1.0f;
        k_agg<<<NTOT, 256>>>(bemb_l + (size_t)l*16*EMB, gin_eps + l, vnp, vnstride, hscale);

        float* s1 = p_sum + (l*2+0)*512;  float* q1 = p_sq + (l*2+0)*512;
        float* s2 = p_sum + (l*2+1)*512;  float* q2 = p_sq + (l*2+1)*512;

        k_mma<<<dim3(2*EMB/BN, NTOT/BM, 1), 256, SMEM_BYTES>>>(
            pzh, pzl, pw1h + (size_t)l*W, pw1l + (size_t)l*W, mlp_b1 + (size_t)l*2*EMB,
            p_t, nullptr, nullptr, nullptr, 0, NTOT, 2*EMB, EMB, 0, 0, 0);
        k_bnstats<<<NTOT/128, 256>>>(p_t, 2*EMB, s1, q1);
        k_bnapplyS<<<NTOT*2*EMB/256, 256>>>(p_t, bn_g + (size_t)l*2*EMB,
                                            bn_b + (size_t)l*2*EMB, s1, q1);

        k_mma<<<dim3(EMB/BN, NTOT/BM, 1), 256, SMEM_BYTES>>>(
            pth, ptl, pw2h + (size_t)l*W, pw2l + (size_t)l*W, mlp_b2 + (size_t)l*EMB,
            p_h2, nullptr, nullptr, nullptr, 0, NTOT, EMB, 2*EMB, 0, 0, 0);
        k_bnstats<<<NTOT/128, 256>>>(p_h2, EMB, s2, q2);
        if (l < NL - 1)
            k_bnapply<<<NE, 256>>>(p_h2, p_h, obn_g + (size_t)l*EMB,
                                   obn_b + (size_t)l*EMB, s2, q2, 1);
        else
            k_bnapply<<<NE, 256>>>(p_h2, out, obn_g + (size_t)l*EMB,
                                   obn_b + (size_t)l*EMB, s2, q2, 0);

        if (l < NL - 1)
            k_vnmlp<<<BG, 256>>>(vn_w1 + (size_t)l*W, vn_b1 + (size_t)l*2*EMB,
                                 vn_w2 + (size_t)l*W, vn_b2 + (size_t)l*EMB,
                                 vnp, vnstride);

        vnp = p_vn; vnstride = EMB;
    }

    (void)in_sizes; (void)out_size;
}

// round 15
// speedup vs baseline: 1.1282x; 1.1282x over previous
#include <cuda_runtime.h>
#include <cuda_bf16.h>
#include <math.h>

#define BG   128
#define NPG  256
#define EPG  2048
#define EMB  256
#define NL   5
#define NTOT (BG*NPG)     // 32768 nodes
#define ETOT (BG*EPG)     // 262144 edges

typedef unsigned long long ull;
typedef __nv_bfloat16 bf16;

// ------------------------------ scratch (device globals; no allocs) ---------
// 32-bit packed adjacency keys: ((edge_idx+1)<<4) | bond_type.
// INVARIANT: all-zero at entry (zero-init at load; k_adjnorm restores zeros).
__device__ unsigned g_pk[(size_t)BG*NPG*NPG];
__device__ float g_cs [BG*NPG];      // rsqrt(col sums)
__device__ float g_rs [BG*NPG];      // rsqrt(row sums)
__device__ float g_h  [NTOT*EMB];
__device__ float g_hin[NTOT*EMB];
__device__ float g_t  [NTOT*2*EMB];
__device__ float g_h2 [NTOT*EMB];
__device__ float g_vn [BG*EMB];
__device__ float g_ewt[16];
__device__ int   g_deg[NTOT];
__device__ int   g_ptr[NTOT];
__device__ int   g_cur[NTOT];
__device__ int   g_csrc[ETOT];
__device__ int   g_cea [ETOT];
// per-(layer,stage) BN stats: slot = l*2+stage, 512 floats per slot
__device__ float g_sum[NL*2*512];
__device__ float g_sq [NL*2*512];

// bf16 hi/lo planes (GEMM operands)
__device__ __align__(16) bf16 g_Ahp[(size_t)BG*NPG*NPG], g_Alp[(size_t)BG*NPG*NPG];
__device__ __align__(16) bf16 g_x1h[NTOT*EMB], g_x1l[NTOT*EMB];
__device__ __align__(16) bf16 g_x2h[NTOT*EMB], g_x2l[NTOT*EMB];
__device__ __align__(16) bf16 g_zh [NTOT*EMB], g_zl [NTOT*EMB];
__device__ __align__(16) bf16 g_th [NTOT*2*EMB], g_tl [NTOT*2*EMB];
__device__ __align__(16) bf16 g_vth[BG*EMB],   g_vtl[BG*EMB];
__device__ __align__(16) bf16 g_vhh[BG*2*EMB], g_vhl[BG*2*EMB];
__device__ __align__(16) bf16 g_w1h[NL*EMB*2*EMB],  g_w1l[NL*EMB*2*EMB];
__device__ __align__(16) bf16 g_w2h[NL*2*EMB*EMB],  g_w2l[NL*2*EMB*EMB];
__device__ __align__(16) bf16 g_u1h[(NL-1)*EMB*2*EMB], g_u1l[(NL-1)*EMB*2*EMB];
__device__ __align__(16) bf16 g_u2h[(NL-1)*2*EMB*EMB], g_u2l[(NL-1)*2*EMB*EMB];

__device__ __forceinline__ void splitw(float v, bf16* __restrict__ h,
                                       bf16* __restrict__ l, size_t i) {
    bf16 hv = __float2bfloat16(v);
    h[i] = hv;
    l[i] = __float2bfloat16(v - __bfloat162float(hv));
}

// ------------------------------ setup kernels -------------------------------
__global__ void k_zero() {
    int i = blockIdx.x * 256 + threadIdx.x;
    if (i < NTOT) g_deg[i] = 0;
    if (i < NL*2*512) { g_sum[i] = 0.f; g_sq[i] = 0.f; }
}

__global__ void k_ewt(const float* __restrict__ bh, const float* __restrict__ w,
                      const float* __restrict__ b) {
    int warp = threadIdx.x >> 5, lane = threadIdx.x & 31;
    if (warp < 16) {
        float v = bh[warp*64 + lane] * w[lane] + bh[warp*64 + 32 + lane] * w[32 + lane];
        #pragma unroll
        for (int o = 16; o; o >>= 1) v += __shfl_down_sync(0xffffffffu, v, o);
        if (lane == 0) g_ewt[warp] = 1.f / (1.f + expf(-(v + b[0])));
    }
}

__global__ void k_scatter(const int* __restrict__ lei, const int* __restrict__ eai) {
    int idx = blockIdx.x * 256 + threadIdx.x;
    if (idx >= ETOT) return;
    int b = idx / EPG, k = idx - b * EPG;
    int s = lei[(size_t)b*2*EPG + k];
    int d = lei[(size_t)b*2*EPG + EPG + k];
    int t = eai[idx];
    unsigned key = ((unsigned)(k + 1) << 4) | (unsigned)t;
    atomicMax(&g_pk[(size_t)b*NPG*NPG + (size_t)s*NPG + d], key);
    atomicAdd(&g_deg[b*NPG + d], 1);
}

__global__ void k_adjprep() {
    int g = blockIdx.x;
    int tid = threadIdx.x, lane = tid & 31, warp = tid >> 5;
    __shared__ float s_cs[NPG], s_rs[NPG];
    for (int i = tid; i < NPG; i += 256) s_cs[i] = 0.f;
    __syncthreads();
    const unsigned* P = g_pk + (size_t)g*NPG*NPG;
    float csl[8] = {};
    for (int rb = 0; rb < NPG; rb += 8) {
        int r = rb + warp;
        float rsum = 0.f;
        #pragma unroll
        for (int k = 0; k < 8; k++) {
            int c = lane + k*32;
            unsigned p = P[(size_t)r*NPG + c];
            float v = p ? g_ewt[p & 15u] : 0.f;
            if (r == c) v += 1.f;
            rsum += v;
            csl[k] += v;
        }
        #pragma unroll
        for (int o = 16; o; o >>= 1) rsum += __shfl_down_sync(0xffffffffu, rsum, o);
        if (lane == 0) s_rs[r] = rsqrtf(rsum);
    }
    #pragma unroll
    for (int k = 0; k < 8; k++) atomicAdd(&s_cs[lane + k*32], csl[k]);
    __syncthreads();
    for (int i = tid; i < NPG; i += 256) {
        g_cs[g*NPG + i] = rsqrtf(s_cs[i]);
        g_rs[g*NPG + i] = s_rs[i];
    }
}

// normalize + split to bf16 planes; restores the zero-pack invariant
__global__ void k_adjnorm() {
    size_t idx = (size_t)blockIdx.x * 256 + threadIdx.x;
    int g = (int)(idx >> 16);
    int r = (int)((idx >> 8) & 255);
    int c = (int)(idx & 255);
    unsigned p = g_pk[idx];
    float v = p ? g_ewt[p & 15u] : 0.f;
    if (p) g_pk[idx] = 0u;
    if (r == c) v += 1.f;
    v *= g_cs[g*NPG + r] * g_rs[g*NPG + c];
    splitw(v, g_Ahp, g_Alp, idx);
}

__global__ void k_scan() {
    int g = blockIdx.x, tid = threadIdx.x;
    __shared__ int s[NPG];
    int d = g_deg[g*NPG + tid];
    s[tid] = d;
    __syncthreads();
    for (int off = 1; off < NPG; off <<= 1) {
        int v = (tid >= off) ? s[tid - off] : 0;
        __syncthreads();
        s[tid] += v;
        __syncthreads();
    }
    int excl = s[tid] - d;
    g_ptr[g*NPG + tid] = g*EPG + excl;
    g_cur[g*NPG + tid] = g*EPG + excl;
}

__global__ void k_csrfill(const int* __restrict__ lei, const int* __restrict__ eai) {
    int idx = blockIdx.x * 256 + threadIdx.x;
    if (idx >= ETOT) return;
    int b = idx / EPG, k = idx - b * EPG;
    int s = lei[(size_t)b*2*EPG + k];
    int d = lei[(size_t)b*2*EPG + EPG + k];
    int pos = atomicAdd(&g_cur[b*NPG + d], 1);
    g_csrc[pos] = b*NPG + s;
    g_cea [pos] = eai[idx];
}

__global__ void k_gather(const int* __restrict__ aidx, const float* __restrict__ aemb) {
    int idx = blockIdx.x * 256 + threadIdx.x;
    int n = idx >> 8, c = idx & 255;
    float v = aemb[aidx[n]*EMB + c];
    g_h[idx] = v;
    splitw(v, g_x1h, g_x1l, idx);
}

__global__ void k_split(const float* __restrict__ w, bf16* __restrict__ h,
                        bf16* __restrict__ l, int n) {
    int i = blockIdx.x * 256 + threadIdx.x;
    if (i < n) splitw(w[i], h, l, i);
}

// ------------------------------ pipelined bf16x3 tensor GEMM ----------------
#define BM 128
#define BN 64
#define APAD 40
#define BPAD 72
#define ASEG (128*APAD)
#define BSEG (32*BPAD)
#define BBASE (6*ASEG)
#define SMEM_BYTES ((6*ASEG + 6*BSEG)*2)   // 89088

__device__ __forceinline__ void cpa16(unsigned s, const void* g) {
    asm volatile("cp.async.cg.shared.global [%0], [%1], 16;" :: "r"(s), "l"(g));
}
#define LDSM4(r0,r1,r2,r3,a)                                                   \
    asm volatile("ldmatrix.sync.aligned.m8n8.x4.shared.b16 {%0,%1,%2,%3}, [%4];" \
        : "=r"(r0),"=r"(r1),"=r"(r2),"=r"(r3) : "r"(a))
#define LDSM4T(r0,r1,r2,r3,a)                                                  \
    asm volatile("ldmatrix.sync.aligned.m8n8.x4.trans.shared.b16 {%0,%1,%2,%3}, [%4];" \
        : "=r"(r0),"=r"(r1),"=r"(r2),"=r"(r3) : "r"(a))
#define MMA_BF16(c, a, b)                                                     \
    asm volatile(                                                             \
        "mma.sync.aligned.m16n8k16.row.col.f32.bf16.bf16.f32 "                \
        "{%0,%1,%2,%3}, {%4,%5,%6,%7}, {%8,%9}, {%0,%1,%2,%3};\n"             \
        : "+f"((c)[0]), "+f"((c)[1]), "+f"((c)[2]), "+f"((c)[3])              \
        : "r"((a)[0]), "r"((a)[1]), "r"((a)[2]), "r"((a)[3]),                 \
          "r"((b)[0]), "r"((b)[1]))

__global__ void __launch_bounds__(256, 2)
k_mma(const bf16* __restrict__ Ah, const bf16* __restrict__ Al,
      const bf16* __restrict__ Bh, const bf16* __restrict__ Bl,
      const float* __restrict__ bias,
      float* __restrict__ Cf, bf16* __restrict__ Chi, bf16* __restrict__ Clo,
      float* __restrict__ Y, int relu,
      int M, int N, int K, long sA, long sB, long sC) {
    extern __shared__ bf16 smbuf[];
    Ah += (size_t)blockIdx.z * sA;  Al += (size_t)blockIdx.z * sA;
    Bh += (size_t)blockIdx.z * sB;  Bl += (size_t)blockIdx.z * sB;
    if (Cf)  Cf  += (size_t)blockIdx.z * sC;
    if (Chi) { Chi += (size_t)blockIdx.z * sC; Clo += (size_t)blockIdx.z * sC; }
    if (Y)   Y   += (size_t)blockIdx.z * sC;

    unsigned sb = (unsigned)__cvta_generic_to_shared(smbuf);
    int tid = threadIdx.x, lane = tid & 31, warp = tid >> 5;
    int wm = warp >> 1, wn = warp & 1;
    int bm = blockIdx.y * BM, bn = blockIdx.x * BN;

    int ar = tid >> 2, ac = (tid & 3) * 8;
    int br = tid >> 3, bc = (tid & 7) * 8;
    int lr = lane & 15, lc = (lane >> 4) * 8;

    float acc[2][4][4];
    #pragma unroll
    for (int i = 0; i < 2; i++)
        #pragma unroll
        for (int j = 0; j < 4; j++)
            #pragma unroll
            for (int r = 0; r < 4; r++) acc[i][j][r] = 0.f;

    int niter = K / 32;

#define ISSUE(buf, kk) {                                                         \
    unsigned a0 = sb + (unsigned)(((buf)*2+0)*ASEG)*2;                            \
    unsigned a1 = sb + (unsigned)(((buf)*2+1)*ASEG)*2;                            \
    unsigned b0 = sb + (unsigned)((BBASE + ((buf)*2+0)*BSEG))*2;                  \
    unsigned b1 = sb + (unsigned)((BBASE + ((buf)*2+1)*BSEG))*2;                  \
    cpa16(a0 + (ar*APAD + ac)*2,      Ah + (size_t)(bm + ar)*K + (kk) + ac);      \
    cpa16(a0 + ((ar+64)*APAD + ac)*2, Ah + (size_t)(bm + ar + 64)*K + (kk) + ac); \
    cpa16(a1 + (ar*APAD + ac)*2,      Al + (size_t)(bm + ar)*K + (kk) + ac);      \
    cpa16(a1 + ((ar+64)*APAD + ac)*2, Al + (size_t)(bm + ar + 64)*K + (kk) + ac); \
    cpa16(b0 + (br*BPAD + bc)*2,      Bh + (size_t)((kk) + br)*N + bn + bc);      \
    cpa16(b1 + (br*BPAD + bc)*2,      Bl + (size_t)((kk) + br)*N + bn + bc);      \
}

    ISSUE(0, 0);
    asm volatile("cp.async.commit_group;");
    ISSUE(1, 32);
    asm volatile("cp.async.commit_group;");

    int cbuf = 0, ibuf = 2;
    for (int it = 0; it < niter; it++) {
        asm volatile("cp.async.wait_group 1;");
        __syncthreads();
        if (it + 2 < niter) { int kk = (it + 2) * 32; ISSUE(ibuf, kk); }
        asm volatile("cp.async.commit_group;");

        unsigned aH = sb + (unsigned)((cbuf*2+0)*ASEG)*2;
        unsigned aL = sb + (unsigned)((cbuf*2+1)*ASEG)*2;
        unsigned bH = sb + (unsigned)((BBASE + (cbuf*2+0)*BSEG))*2;
        unsigned bL = sb + (unsigned)((BBASE + (cbuf*2+1)*BSEG))*2;

        #pragma unroll
        for (int ks = 0; ks < 2; ks++) {
            unsigned ah[2][4], al[2][4], bh[4][2], bl[4][2];
            #pragma unroll
            for (int mf = 0; mf < 2; mf++) {
                unsigned off = (unsigned)(((wm*32 + mf*16 + lr)*APAD + ks*16 + lc)*2);
                LDSM4(ah[mf][0], ah[mf][1], ah[mf][2], ah[mf][3], aH + off);
                LDSM4(al[mf][0], al[mf][1], al[mf][2], al[mf][3], aL + off);
            }
            #pragma unroll
            for (int p = 0; p < 2; p++) {
                unsigned off = (unsigned)(((ks*16 + lr)*BPAD + wn*32 + p*16 + lc)*2);
                unsigned r0, r1, r2, r3;
                LDSM4T(r0, r1, r2, r3, bH + off);
                bh[2*p][0] = r0; bh[2*p][1] = r1; bh[2*p+1][0] = r2; bh[2*p+1][1] = r3;
                LDSM4T(r0, r1, r2, r3, bL + off);
                bl[2*p][0] = r0; bl[2*p][1] = r1; bl[2*p+1][0] = r2; bl[2*p+1][1] = r3;
            }
            #pragma unroll
            for (int mf = 0; mf < 2; mf++)
                #pragma unroll
                for (int nf = 0; nf < 4; nf++) {
                    float* c = acc[mf][nf];
                    MMA_BF16(c, ah[mf], bl[nf]);
                    MMA_BF16(c, al[mf], bh[nf]);
                    MMA_BF16(c, ah[mf], bh[nf]);
                }
        }
        cbuf = (cbuf == 2) ? 0 : cbuf + 1;
        ibuf = (ibuf == 2) ? 0 : ibuf + 1;
    }

    // ---- epilogue ----
    int gid = lane >> 2, tig = lane & 3;
    #pragma unroll
    for (int mf = 0; mf < 2; mf++) {
        #pragma unroll
        for (int nf = 0; nf < 4; nf++) {
            int r0 = bm + wm*32 + mf*16 + gid;
            int c0 = bn + wn*32 + nf*8 + 2*tig;
            float b0 = 0.f, b1 = 0.f;
            if (bias) { b0 = bias[c0]; b1 = bias[c0+1]; }
            float* c = acc[mf][nf];
            #pragma unroll
            for (int half = 0; half < 2; half++) {
                int r = r0 + half*8;
                float v0 = c[half*2+0] + b0, v1 = c[half*2+1] + b1;
                if (relu) { v0 = fmaxf(v0, 0.f); v1 = fmaxf(v1, 0.f); }
                if (Cf)
                    *reinterpret_cast<float2*>(Cf + (size_t)r*N + c0) = make_float2(v0, v1);
                if (Chi) {
                    bf16 h0 = __float2bfloat16(v0), h1 = __float2bfloat16(v1);
                    *reinterpret_cast<__nv_bfloat162*>(Chi + (size_t)r*N + c0) =
                        __halves2bfloat162(h0, h1);
                    bf16 l0 = __float2bfloat16(v0 - __bfloat162float(h0));
                    bf16 l1 = __float2bfloat16(v1 - __bfloat162float(h1));
                    *reinterpret_cast<__nv_bfloat162*>(Clo + (size_t)r*N + c0) =
                        __halves2bfloat162(l0, l1);
                }
                if (Y) {
                    float2* y = reinterpret_cast<float2*>(Y + (size_t)r*N + c0);
                    float2 yo = *y;
                    yo.x += v0; yo.y += v1;
                    *y = yo;
                }
            }
        }
    }
#undef ISSUE
}

// ------------------------------ fused GIN aggregate --------------------------
__global__ void k_agg(const float* __restrict__ eembL, const float* __restrict__ epsp,
                      const float* __restrict__ vnp, int vnstride, float hscale) {
    int n = blockIdx.x, c = threadIdx.x;
    int b = n >> 8;
    float vnv = vnp[b*vnstride + c];
    int start = g_ptr[n], deg = g_deg[n];
    float own = g_h[(size_t)n*EMB + c] * hscale + vnv;
    g_hin[(size_t)n*EMB + c] = own;
    float val = 0.f;
    for (int k = 0; k < deg; k++) {
        int s = g_csrc[start + k];
        int t = g_cea [start + k];
        float m = g_h[(size_t)s*EMB + c] * hscale + vnv + eembL[t*EMB + c];
        val += fmaxf(m, 0.f);
    }
    float z = (1.f + *epsp) * own + val;
    splitw(z, g_zh, g_zl, (size_t)n*EMB + c);
}

// ------------------------------ batchnorm -----------------------------------
// 64 rows per block (512 blocks) for 2x the inflight parallelism
__global__ void k_bnstats(const float* __restrict__ X, int C,
                          float* __restrict__ sum, float* __restrict__ sq) {
    int r0 = blockIdx.x * 64;
    for (int c = threadIdx.x; c < C; c += 256) {
        float s = 0.f, q = 0.f;
        for (int r = 0; r < 64; r++) {
            float v = X[(size_t)(r0 + r)*C + c];
            s += v; q += v * v;
        }
        atomicAdd(&sum[c], s);
        atomicAdd(&sq[c], q);
    }
}

__device__ __forceinline__ void bn_coef(const float* __restrict__ sum,
                                        const float* __restrict__ sq,
                                        const float* __restrict__ gamma,
                                        const float* __restrict__ beta,
                                        int c, float& sc, float& sh) {
    float mu  = sum[c] * (1.f / NTOT);
    float var = sq[c] * (1.f / NTOT) - mu * mu;
    sc = gamma[c] * rsqrtf(var + 1e-5f);
    sh = beta[c] - mu * sc;
}

// BN1 apply + relu -> bf16 planes (feeds GEMM2); scale/shift computed inline
__global__ void k_bnapplyS(const float* __restrict__ X,
                           const float* __restrict__ gamma, const float* __restrict__ beta,
                           const float* __restrict__ sum, const float* __restrict__ sq) {
    int idx = blockIdx.x * 256 + threadIdx.x;
    int c = idx & (2*EMB - 1);
    float sc, sh;
    bn_coef(sum, sq, gamma, beta, c, sc, sh);
    float v = fmaxf(X[idx] * sc + sh, 0.f);
    splitw(v, g_th, g_tl, idx);
}

// BN2 apply -> fp32 (h for next layer, or final output)
__global__ void k_bnapply(const float* __restrict__ X, float* __restrict__ O,
                          const float* __restrict__ gamma, const float* __restrict__ beta,
                          const float* __restrict__ sum, const float* __restrict__ sq,
                          int act) {
    int idx = blockIdx.x * 256 + threadIdx.x;
    int c = idx & 255;
    float sc, sh;
    bn_coef(sum, sq, gamma, beta, c, sc, sh);
    float v = X[idx] * sc + sh;
    if (act) v = fmaxf(v, 0.f);
    O[idx] = v;
}

// vt[b] = sum_nodes hin + vn[b]
__global__ void k_vt(const float* __restrict__ vnp, int vnstride) {
    int b = blockIdx.x, c = threadIdx.x;
    const float* base = g_hin + (size_t)b*NPG*EMB + c;
    float s = 0.f;
    #pragma unroll 4
    for (int r = 0; r < NPG; r++) s += base[(size_t)r*EMB];
    splitw(s + vnp[b*vnstride + c], g_vth, g_vtl, b*EMB + c);
}

// ------------------------------ host orchestration --------------------------
extern "C" void kernel_launch(void* const* d_in, const int* in_sizes, int n_in,
                              void* d_out, int out_size) {
    const int ab = n_in - 19;
    const int*   atom_idx = (const int*)  d_in[0];
    const int*   lei      = (const int*)  d_in[1];
    const int*   eai      = (const int*)  d_in[2];
    const float* atom_emb = (const float*)d_in[ab + 0];
    const float* bemb_h   = (const float*)d_in[ab + 1];
    const float* elin_w   = (const float*)d_in[ab + 2];
    const float* elin_b   = (const float*)d_in[ab + 3];
    const float* bemb_l   = (const float*)d_in[ab + 4];
    const float* gin_eps  = (const float*)d_in[ab + 5];
    const float* mlp_w1   = (const float*)d_in[ab + 6];
    const float* mlp_b1   = (const float*)d_in[ab + 7];
    const float* bn_g     = (const float*)d_in[ab + 8];
    const float* bn_b     = (const float*)d_in[ab + 9];
    const float* mlp_w2   = (const float*)d_in[ab + 10];
    const float* mlp_b2   = (const float*)d_in[ab + 11];
    const float* obn_g    = (const float*)d_in[ab + 12];
    const float* obn_b    = (const float*)d_in[ab + 13];
    const float* vn_emb   = (const float*)d_in[ab + 14];
    const float* vn_w1    = (const float*)d_in[ab + 15];
    const float* vn_b1    = (const float*)d_in[ab + 16];
    const float* vn_w2    = (const float*)d_in[ab + 17];
    const float* vn_b2    = (const float*)d_in[ab + 18];
    float* out = (float*)d_out;

    static int smem_set = 0;
    if (!smem_set) {
        cudaFuncSetAttribute(k_mma, cudaFuncAttributeMaxDynamicSharedMemorySize, SMEM_BYTES);
        smem_set = 1;
    }

    float *p_t, *p_h2, *p_h, *p_vn, *p_sum, *p_sq;
    cudaGetSymbolAddress((void**)&p_t,  g_t);
    cudaGetSymbolAddress((void**)&p_h2, g_h2);
    cudaGetSymbolAddress((void**)&p_h,  g_h);
    cudaGetSymbolAddress((void**)&p_vn, g_vn);
    cudaGetSymbolAddress((void**)&p_sum, g_sum);
    cudaGetSymbolAddress((void**)&p_sq,  g_sq);
    bf16 *pAh, *pAl, *px1h, *px1l, *px2h, *px2l, *pzh, *pzl, *pth, *ptl;
    bf16 *pvth, *pvtl, *pvhh, *pvhl, *pw1h, *pw1l, *pw2h, *pw2l, *pu1h, *pu1l, *pu2h, *pu2l;
    cudaGetSymbolAddress((void**)&pAh,  g_Ahp);
    cudaGetSymbolAddress((void**)&pAl,  g_Alp);
    cudaGetSymbolAddress((void**)&px1h, g_x1h);
    cudaGetSymbolAddress((void**)&px1l, g_x1l);
    cudaGetSymbolAddress((void**)&px2h, g_x2h);
    cudaGetSymbolAddress((void**)&px2l, g_x2l);
    cudaGetSymbolAddress((void**)&pzh,  g_zh);
    cudaGetSymbolAddress((void**)&pzl,  g_zl);
    cudaGetSymbolAddress((void**)&pth,  g_th);
    cudaGetSymbolAddress((void**)&ptl,  g_tl);
    cudaGetSymbolAddress((void**)&pvth, g_vth);
    cudaGetSymbolAddress((void**)&pvtl, g_vtl);
    cudaGetSymbolAddress((void**)&pvhh, g_vhh);
    cudaGetSymbolAddress((void**)&pvhl, g_vhl);
    cudaGetSymbolAddress((void**)&pw1h, g_w1h);
    cudaGetSymbolAddress((void**)&pw1l, g_w1l);
    cudaGetSymbolAddress((void**)&pw2h, g_w2h);
    cudaGetSymbolAddress((void**)&pw2l, g_w2l);
    cudaGetSymbolAddress((void**)&pu1h, g_u1h);
    cudaGetSymbolAddress((void**)&pu1l, g_u1l);
    cudaGetSymbolAddress((void**)&pu2h, g_u2h);
    cudaGetSymbolAddress((void**)&pu2l, g_u2l);

    const int NE = NTOT*EMB/256;
    const int W  = EMB*2*EMB;

    // ---- setup ----
    k_zero<<<NTOT/256, 256>>>();
    k_ewt<<<1, 512>>>(bemb_h, elin_w, elin_b);
    k_scatter<<<ETOT/256, 256>>>(lei, eai);
    k_adjprep<<<BG, 256>>>();
    k_adjnorm<<<(int)((size_t)BG*NPG*NPG/256), 256>>>();
    k_scan<<<BG, 256>>>();
    k_csrfill<<<ETOT/256, 256>>>(lei, eai);
    k_gather<<<NE, 256>>>(atom_idx, atom_emb);
    k_split<<<NL*W/256, 256>>>(mlp_w1, pw1h, pw1l, NL*W);
    k_split<<<NL*W/256, 256>>>(mlp_w2, pw2h, pw2l, NL*W);
    k_split<<<(NL-1)*W/256, 256>>>(vn_w1, pu1h, pu1l, (NL-1)*W);
    k_split<<<(NL-1)*W/256, 256>>>(vn_w2, pu2h, pu2l, (NL-1)*W);

    // ---- propagation: g_h accumulates f + Af + A^2 f + A^3 f ----
    dim3 pg(EMB/BN, NPG/BM, BG);
    long sAdj = (long)NPG*NPG, sX = (long)NPG*EMB;
    k_mma<<<pg, 256, SMEM_BYTES>>>(pAh, pAl, px1h, px1l, nullptr,
                                   nullptr, px2h, px2l, p_h, 0, NPG, EMB, NPG, sAdj, sX, sX);
    k_mma<<<pg, 256, SMEM_BYTES>>>(pAh, pAl, px2h, px2l, nullptr,
                                   nullptr, px1h, px1l, p_h, 0, NPG, EMB, NPG, sAdj, sX, sX);
    k_mma<<<pg, 256, SMEM_BYTES>>>(pAh, pAl, px1h, px1l, nullptr,
                                   nullptr, px2h, px2l, p_h, 0, NPG, EMB, NPG, sAdj, sX, sX);

    // ---- GIN + virtual-node stack ----
    const float* vnp = vn_emb;
    int vnstride = 0;

    for (int l = 0; l < NL; l++) {
        float hscale = (l == 0) ? 0.25f : 1.0f;
        k_agg<<<NTOT, 256>>>(bemb_l + (size_t)l*16*EMB, gin_eps + l, vnp, vnstride, hscale);

        float* s1 = p_sum + (l*2+0)*512;  float* q1 = p_sq + (l*2+0)*512;
        float* s2 = p_sum + (l*2+1)*512;  float* q2 = p_sq + (l*2+1)*512;

        // GEMM1: t = z @ w1 + b1  [N, 512] fp32
        k_mma<<<dim3(2*EMB/BN, NTOT/BM, 1), 256, SMEM_BYTES>>>(
            pzh, pzl, pw1h + (size_t)l*W, pw1l + (size_t)l*W, mlp_b1 + (size_t)l*2*EMB,
            p_t, nullptr, nullptr, nullptr, 0, NTOT, 2*EMB, EMB, 0, 0, 0);
        k_bnstats<<<NTOT/64, 256>>>(p_t, 2*EMB, s1, q1);
        k_bnapplyS<<<NTOT*2*EMB/256, 256>>>(p_t, bn_g + (size_t)l*2*EMB,
                                            bn_b + (size_t)l*2*EMB, s1, q1);

        // GEMM2: h2 = t' @ w2 + b2  [N, 256] fp32
        k_mma<<<dim3(EMB/BN, NTOT/BM, 1), 256, SMEM_BYTES>>>(
            pth, ptl, pw2h + (size_t)l*W, pw2l + (size_t)l*W, mlp_b2 + (size_t)l*EMB,
            p_h2, nullptr, nullptr, nullptr, 0, NTOT, EMB, 2*EMB, 0, 0, 0);
        k_bnstats<<<NTOT/64, 256>>>(p_h2, EMB, s2, q2);
        if (l < NL - 1)
            k_bnapply<<<NE, 256>>>(p_h2, p_h, obn_g + (size_t)l*EMB,
                                   obn_b + (size_t)l*EMB, s2, q2, 1);
        else
            k_bnapply<<<NE, 256>>>(p_h2, out, obn_g + (size_t)l*EMB,
                                   obn_b + (size_t)l*EMB, s2, q2, 0);

        // virtual node update
        if (l < NL - 1) {
            k_vt<<<BG, 256>>>(vnp, vnstride);
            k_mma<<<dim3(2*EMB/BN, 1, 1), 256, SMEM_BYTES>>>(
                pvth, pvtl, pu1h + (size_t)l*W, pu1l + (size_t)l*W, vn_b1 + (size_t)l*2*EMB,
                nullptr, pvhh, pvhl, nullptr, 1, 128, 2*EMB, EMB, 0, 0, 0);
            k_mma<<<dim3(EMB/BN, 1, 1), 256, SMEM_BYTES>>>(
                pvhh, pvhl, pu2h + (size_t)l*W, pu2l + (size_t)l*W, vn_b2 + (size_t)l*EMB,
                p_vn, nullptr, nullptr, nullptr, 1, 128, EMB, 2*EMB, 0, 0, 0);
        }

        vnp = p_vn; vnstride = EMB;
    }

    (void)in_sizes; (void)out_size;
}

// round 16
// speedup vs baseline: 1.1556x; 1.0243x over previous
#include <cuda_runtime.h>
#include <cuda_bf16.h>
#include <math.h>

#define BG   128
#define NPG  256
#define EPG  2048
#define EMB  256
#define NL   5
#define NTOT (BG*NPG)     // 32768 nodes
#define ETOT (BG*EPG)     // 262144 edges

typedef unsigned long long ull;
typedef __nv_bfloat16 bf16;

// ------------------------------ scratch (device globals; no allocs) ---------
// 32-bit packed adjacency keys: ((edge_idx+1)<<4) | bond_type.
// INVARIANT: all-zero at entry (zero-init at load; k_adjnorm restores zeros).
__device__ unsigned g_pk[(size_t)BG*NPG*NPG];
__device__ float g_cs [BG*NPG];      // raw col sums -> rsqrt'd by k_scan
__device__ float g_rs [BG*NPG];      // rsqrt(row sums)
__device__ float g_h  [NTOT*EMB];
__device__ float g_hin[NTOT*EMB];
__device__ float g_t  [NTOT*2*EMB];
__device__ float g_h2 [NTOT*EMB];
__device__ float g_vn [BG*EMB];
__device__ float g_ewt[16];
__device__ int   g_deg[NTOT];
__device__ int   g_ptr[NTOT];
__device__ int   g_cur[NTOT];
__device__ int   g_csrc[ETOT];
__device__ int   g_cea [ETOT];
// per-(layer,stage) BN stats: slot = l*2+stage, 512 floats per slot
__device__ float g_sum[NL*2*512];
__device__ float g_sq [NL*2*512];

// bf16 hi/lo planes (GEMM operands)
__device__ __align__(16) bf16 g_Ahp[(size_t)BG*NPG*NPG], g_Alp[(size_t)BG*NPG*NPG];
__device__ __align__(16) bf16 g_x1h[NTOT*EMB], g_x1l[NTOT*EMB];
__device__ __align__(16) bf16 g_x2h[NTOT*EMB], g_x2l[NTOT*EMB];
__device__ __align__(16) bf16 g_zh [NTOT*EMB], g_zl [NTOT*EMB];
__device__ __align__(16) bf16 g_th [NTOT*2*EMB], g_tl [NTOT*2*EMB];
__device__ __align__(16) bf16 g_vth[BG*EMB],   g_vtl[BG*EMB];
__device__ __align__(16) bf16 g_vhh[BG*2*EMB], g_vhl[BG*2*EMB];
__device__ __align__(16) bf16 g_w1h[NL*EMB*2*EMB],  g_w1l[NL*EMB*2*EMB];
__device__ __align__(16) bf16 g_w2h[NL*2*EMB*EMB],  g_w2l[NL*2*EMB*EMB];
__device__ __align__(16) bf16 g_u1h[(NL-1)*EMB*2*EMB], g_u1l[(NL-1)*EMB*2*EMB];
__device__ __align__(16) bf16 g_u2h[(NL-1)*2*EMB*EMB], g_u2l[(NL-1)*2*EMB*EMB];

__device__ __forceinline__ void splitw(float v, bf16* __restrict__ h,
                                       bf16* __restrict__ l, size_t i) {
    bf16 hv = __float2bfloat16(v);
    h[i] = hv;
    l[i] = __float2bfloat16(v - __bfloat162float(hv));
}

// ------------------------------ setup kernels -------------------------------
__global__ void k_zero() {
    int i = blockIdx.x * 256 + threadIdx.x;
    if (i < NTOT) { g_deg[i] = 0; g_cs[i] = 0.f; }
    if (i < NL*2*512) { g_sum[i] = 0.f; g_sq[i] = 0.f; }
}

__global__ void k_ewt(const float* __restrict__ bh, const float* __restrict__ w,
                      const float* __restrict__ b) {
    int warp = threadIdx.x >> 5, lane = threadIdx.x & 31;
    if (warp < 16) {
        float v = bh[warp*64 + lane] * w[lane] + bh[warp*64 + 32 + lane] * w[32 + lane];
        #pragma unroll
        for (int o = 16; o; o >>= 1) v += __shfl_down_sync(0xffffffffu, v, o);
        if (lane == 0) g_ewt[warp] = 1.f / (1.f + expf(-(v + b[0])));
    }
}

__global__ void k_scatter(const int* __restrict__ lei, const int* __restrict__ eai) {
    int idx = blockIdx.x * 256 + threadIdx.x;
    if (idx >= ETOT) return;
    int b = idx / EPG, k = idx - b * EPG;
    int s = lei[(size_t)b*2*EPG + k];
    int d = lei[(size_t)b*2*EPG + EPG + k];
    int t = eai[idx];
    unsigned key = ((unsigned)(k + 1) << 4) | (unsigned)t;
    atomicMax(&g_pk[(size_t)b*NPG*NPG + (size_t)s*NPG + d], key);
    atomicAdd(&g_deg[b*NPG + d], 1);
}

// per-graph row/col sums of (adj + I); 4 blocks per graph (64 rows each)
// g_rs written as rsqrt(rowsum); g_cs accumulates RAW column sums.
__global__ void k_adjprep() {
    int blk = blockIdx.x;
    int g = blk >> 2, q = blk & 3;      // quarter index
    int tid = threadIdx.x, lane = tid & 31, warp = tid >> 5;
    __shared__ float s_cs[NPG];
    for (int i = tid; i < NPG; i += 256) s_cs[i] = 0.f;
    __syncthreads();
    const unsigned* P = g_pk + (size_t)g*NPG*NPG;
    int r0 = q * 64;
    float csl[8] = {};
    for (int rb = 0; rb < 64; rb += 8) {
        int r = r0 + rb + warp;
        float rsum = 0.f;
        #pragma unroll
        for (int k = 0; k < 8; k++) {
            int c = lane + k*32;
            unsigned p = P[(size_t)r*NPG + c];
            float v = p ? g_ewt[p & 15u] : 0.f;
            if (r == c) v += 1.f;
            rsum += v;
            csl[k] += v;
        }
        #pragma unroll
        for (int o = 16; o; o >>= 1) rsum += __shfl_down_sync(0xffffffffu, rsum, o);
        if (lane == 0) g_rs[g*NPG + r] = rsqrtf(rsum);
    }
    #pragma unroll
    for (int k = 0; k < 8; k++) atomicAdd(&s_cs[lane + k*32], csl[k]);
    __syncthreads();
    for (int i = tid; i < NPG; i += 256)
        atomicAdd(&g_cs[g*NPG + i], s_cs[i]);
}

// degree scan -> CSR ptrs; ALSO finalizes g_cs: raw colsum -> rsqrt
__global__ void k_scan() {
    int g = blockIdx.x, tid = threadIdx.x;
    g_cs[g*NPG + tid] = rsqrtf(g_cs[g*NPG + tid]);
    __shared__ int s[NPG];
    int d = g_deg[g*NPG + tid];
    s[tid] = d;
    __syncthreads();
    for (int off = 1; off < NPG; off <<= 1) {
        int v = (tid >= off) ? s[tid - off] : 0;
        __syncthreads();
        s[tid] += v;
        __syncthreads();
    }
    int excl = s[tid] - d;
    g_ptr[g*NPG + tid] = g*EPG + excl;
    g_cur[g*NPG + tid] = g*EPG + excl;
}

// normalize + split to bf16 planes; restores the zero-pack invariant
__global__ void k_adjnorm() {
    size_t idx = (size_t)blockIdx.x * 256 + threadIdx.x;
    int g = (int)(idx >> 16);
    int r = (int)((idx >> 8) & 255);
    int c = (int)(idx & 255);
    unsigned p = g_pk[idx];
    float v = p ? g_ewt[p & 15u] : 0.f;
    if (p) g_pk[idx] = 0u;
    if (r == c) v += 1.f;
    v *= g_cs[g*NPG + r] * g_rs[g*NPG + c];
    splitw(v, g_Ahp, g_Alp, idx);
}

__global__ void k_csrfill(const int* __restrict__ lei, const int* __restrict__ eai) {
    int idx = blockIdx.x * 256 + threadIdx.x;
    if (idx >= ETOT) return;
    int b = idx / EPG, k = idx - b * EPG;
    int s = lei[(size_t)b*2*EPG + k];
    int d = lei[(size_t)b*2*EPG + EPG + k];
    int pos = atomicAdd(&g_cur[b*NPG + d], 1);
    g_csrc[pos] = b*NPG + s;
    g_cea [pos] = eai[idx];
}

__global__ void k_gather(const int* __restrict__ aidx, const float* __restrict__ aemb) {
    int idx = blockIdx.x * 256 + threadIdx.x;
    int n = idx >> 8, c = idx & 255;
    float v = aemb[aidx[n]*EMB + c];
    g_h[idx] = v;
    splitw(v, g_x1h, g_x1l, idx);
}

__global__ void k_split(const float* __restrict__ w, bf16* __restrict__ h,
                        bf16* __restrict__ l, int n) {
    int i = blockIdx.x * 256 + threadIdx.x;
    if (i < n) splitw(w[i], h, l, i);
}

// ------------------------------ pipelined bf16x3 tensor GEMM ----------------
#define BM 128
#define BN 64
#define APAD 40
#define BPAD 72
#define ASEG (128*APAD)
#define BSEG (32*BPAD)
#define BBASE (6*ASEG)
#define SMEM_BYTES ((6*ASEG + 6*BSEG)*2)   // 89088

__device__ __forceinline__ void cpa16(unsigned s, const void* g) {
    asm volatile("cp.async.cg.shared.global [%0], [%1], 16;" :: "r"(s), "l"(g));
}
#define LDSM4(r0,r1,r2,r3,a)                                                   \
    asm volatile("ldmatrix.sync.aligned.m8n8.x4.shared.b16 {%0,%1,%2,%3}, [%4];" \
        : "=r"(r0),"=r"(r1),"=r"(r2),"=r"(r3) : "r"(a))
#define LDSM4T(r0,r1,r2,r3,a)                                                  \
    asm volatile("ldmatrix.sync.aligned.m8n8.x4.trans.shared.b16 {%0,%1,%2,%3}, [%4];" \
        : "=r"(r0),"=r"(r1),"=r"(r2),"=r"(r3) : "r"(a))
#define MMA_BF16(c, a, b)                                                     \
    asm volatile(                                                             \
        "mma.sync.aligned.m16n8k16.row.col.f32.bf16.bf16.f32 "                \
        "{%0,%1,%2,%3}, {%4,%5,%6,%7}, {%8,%9}, {%0,%1,%2,%3};\n"             \
        : "+f"((c)[0]), "+f"((c)[1]), "+f"((c)[2]), "+f"((c)[3])              \
        : "r"((a)[0]), "r"((a)[1]), "r"((a)[2]), "r"((a)[3]),                 \
          "r"((b)[0]), "r"((b)[1]))

__global__ void __launch_bounds__(256, 2)
k_mma(const bf16* __restrict__ Ah, const bf16* __restrict__ Al,
      const bf16* __restrict__ Bh, const bf16* __restrict__ Bl,
      const float* __restrict__ bias,
      float* __restrict__ Cf, bf16* __restrict__ Chi, bf16* __restrict__ Clo,
      float* __restrict__ Y, int relu,
      int M, int N, int K, long sA, long sB, long sC) {
    extern __shared__ bf16 smbuf[];
    Ah += (size_t)blockIdx.z * sA;  Al += (size_t)blockIdx.z * sA;
    Bh += (size_t)blockIdx.z * sB;  Bl += (size_t)blockIdx.z * sB;
    if (Cf)  Cf  += (size_t)blockIdx.z * sC;
    if (Chi) { Chi += (size_t)blockIdx.z * sC; Clo += (size_t)blockIdx.z * sC; }
    if (Y)   Y   += (size_t)blockIdx.z * sC;

    unsigned sb = (unsigned)__cvta_generic_to_shared(smbuf);
    int tid = threadIdx.x, lane = tid & 31, warp = tid >> 5;
    int wm = warp >> 1, wn = warp & 1;
    int bm = blockIdx.y * BM, bn = blockIdx.x * BN;

    int ar = tid >> 2, ac = (tid & 3) * 8;
    int br = tid >> 3, bc = (tid & 7) * 8;
    int lr = lane & 15, lc = (lane >> 4) * 8;

    float acc[2][4][4];
    #pragma unroll
    for (int i = 0; i < 2; i++)
        #pragma unroll
        for (int j = 0; j < 4; j++)
            #pragma unroll
            for (int r = 0; r < 4; r++) acc[i][j][r] = 0.f;

    int niter = K / 32;

#define ISSUE(buf, kk) {                                                         \
    unsigned a0 = sb + (unsigned)(((buf)*2+0)*ASEG)*2;                            \
    unsigned a1 = sb + (unsigned)(((buf)*2+1)*ASEG)*2;                            \
    unsigned b0 = sb + (unsigned)((BBASE + ((buf)*2+0)*BSEG))*2;                  \
    unsigned b1 = sb + (unsigned)((BBASE + ((buf)*2+1)*BSEG))*2;                  \
    cpa16(a0 + (ar*APAD + ac)*2,      Ah + (size_t)(bm + ar)*K + (kk) + ac);      \
    cpa16(a0 + ((ar+64)*APAD + ac)*2, Ah + (size_t)(bm + ar + 64)*K + (kk) + ac); \
    cpa16(a1 + (ar*APAD + ac)*2,      Al + (size_t)(bm + ar)*K + (kk) + ac);      \
    cpa16(a1 + ((ar+64)*APAD + ac)*2, Al + (size_t)(bm + ar + 64)*K + (kk) + ac); \
    cpa16(b0 + (br*BPAD + bc)*2,      Bh + (size_t)((kk) + br)*N + bn + bc);      \
    cpa16(b1 + (br*BPAD + bc)*2,      Bl + (size_t)((kk) + br)*N + bn + bc);      \
}

    ISSUE(0, 0);
    asm volatile("cp.async.commit_group;");
    ISSUE(1, 32);
    asm volatile("cp.async.commit_group;");

    int cbuf = 0, ibuf = 2;
    for (int it = 0; it < niter; it++) {
        asm volatile("cp.async.wait_group 1;");
        __syncthreads();
        if (it + 2 < niter) { int kk = (it + 2) * 32; ISSUE(ibuf, kk); }
        asm volatile("cp.async.commit_group;");

        unsigned aH = sb + (unsigned)((cbuf*2+0)*ASEG)*2;
        unsigned aL = sb + (unsigned)((cbuf*2+1)*ASEG)*2;
        unsigned bH = sb + (unsigned)((BBASE + (cbuf*2+0)*BSEG))*2;
        unsigned bL = sb + (unsigned)((BBASE + (cbuf*2+1)*BSEG))*2;

        #pragma unroll
        for (int ks = 0; ks < 2; ks++) {
            unsigned ah[2][4], al[2][4], bh[4][2], bl[4][2];
            #pragma unroll
            for (int mf = 0; mf < 2; mf++) {
                unsigned off = (unsigned)(((wm*32 + mf*16 + lr)*APAD + ks*16 + lc)*2);
                LDSM4(ah[mf][0], ah[mf][1], ah[mf][2], ah[mf][3], aH + off);
                LDSM4(al[mf][0], al[mf][1], al[mf][2], al[mf][3], aL + off);
            }
            #pragma unroll
            for (int p = 0; p < 2; p++) {
                unsigned off = (unsigned)(((ks*16 + lr)*BPAD + wn*32 + p*16 + lc)*2);
                unsigned r0, r1, r2, r3;
                LDSM4T(r0, r1, r2, r3, bH + off);
                bh[2*p][0] = r0; bh[2*p][1] = r1; bh[2*p+1][0] = r2; bh[2*p+1][1] = r3;
                LDSM4T(r0, r1, r2, r3, bL + off);
                bl[2*p][0] = r0; bl[2*p][1] = r1; bl[2*p+1][0] = r2; bl[2*p+1][1] = r3;
            }
            #pragma unroll
            for (int mf = 0; mf < 2; mf++)
                #pragma unroll
                for (int nf = 0; nf < 4; nf++) {
                    float* c = acc[mf][nf];
                    MMA_BF16(c, ah[mf], bl[nf]);
                    MMA_BF16(c, al[mf], bh[nf]);
                    MMA_BF16(c, ah[mf], bh[nf]);
                }
        }
        cbuf = (cbuf == 2) ? 0 : cbuf + 1;
        ibuf = (ibuf == 2) ? 0 : ibuf + 1;
    }

    // ---- epilogue ----
    int gid = lane >> 2, tig = lane & 3;
    #pragma unroll
    for (int mf = 0; mf < 2; mf++) {
        #pragma unroll
        for (int nf = 0; nf < 4; nf++) {
            int r0 = bm + wm*32 + mf*16 + gid;
            int c0 = bn + wn*32 + nf*8 + 2*tig;
            float b0 = 0.f, b1 = 0.f;
            if (bias) { b0 = bias[c0]; b1 = bias[c0+1]; }
            float* c = acc[mf][nf];
            #pragma unroll
            for (int half = 0; half < 2; half++) {
                int r = r0 + half*8;
                float v0 = c[half*2+0] + b0, v1 = c[half*2+1] + b1;
                if (relu) { v0 = fmaxf(v0, 0.f); v1 = fmaxf(v1, 0.f); }
                if (Cf)
                    *reinterpret_cast<float2*>(Cf + (size_t)r*N + c0) = make_float2(v0, v1);
                if (Chi) {
                    bf16 h0 = __float2bfloat16(v0), h1 = __float2bfloat16(v1);
                    *reinterpret_cast<__nv_bfloat162*>(Chi + (size_t)r*N + c0) =
                        __halves2bfloat162(h0, h1);
                    bf16 l0 = __float2bfloat16(v0 - __bfloat162float(h0));
                    bf16 l1 = __float2bfloat16(v1 - __bfloat162float(h1));
                    *reinterpret_cast<__nv_bfloat162*>(Clo + (size_t)r*N + c0) =
                        __halves2bfloat162(l0, l1);
                }
                if (Y) {
                    float2* y = reinterpret_cast<float2*>(Y + (size_t)r*N + c0);
                    float2 yo = *y;
                    yo.x += v0; yo.y += v1;
                    *y = yo;
                }
            }
        }
    }
#undef ISSUE
}

// ------------------------------ fused GIN aggregate --------------------------
__global__ void k_agg(const float* __restrict__ eembL, const float* __restrict__ epsp,
                      const float* __restrict__ vnp, int vnstride, float hscale) {
    int n = blockIdx.x, c = threadIdx.x;
    int b = n >> 8;
    float vnv = vnp[b*vnstride + c];
    int start = g_ptr[n], deg = g_deg[n];
    float own = g_h[(size_t)n*EMB + c] * hscale + vnv;
    g_hin[(size_t)n*EMB + c] = own;
    float val = 0.f;
    for (int k = 0; k < deg; k++) {
        int s = g_csrc[start + k];
        int t = g_cea [start + k];
        float m = g_h[(size_t)s*EMB + c] * hscale + vnv + eembL[t*EMB + c];
        val += fmaxf(m, 0.f);
    }
    float z = (1.f + *epsp) * own + val;
    splitw(z, g_zh, g_zl, (size_t)n*EMB + c);
}

// ------------------------------ batchnorm -----------------------------------
// 64 rows per block (512 blocks) for latency hiding
__global__ void k_bnstats(const float* __restrict__ X, int C,
                          float* __restrict__ sum, float* __restrict__ sq) {
    int r0 = blockIdx.x * 64;
    for (int c = threadIdx.x; c < C; c += 256) {
        float s = 0.f, q = 0.f;
        for (int r = 0; r < 64; r++) {
            float v = X[(size_t)(r0 + r)*C + c];
            s += v; q += v * v;
        }
        atomicAdd(&sum[c], s);
        atomicAdd(&sq[c], q);
    }
}

__device__ __forceinline__ void bn_coef(const float* __restrict__ sum,
                                        const float* __restrict__ sq,
                                        const float* __restrict__ gamma,
                                        const float* __restrict__ beta,
                                        int c, float& sc, float& sh) {
    float mu  = sum[c] * (1.f / NTOT);
    float var = sq[c] * (1.f / NTOT) - mu * mu;
    sc = gamma[c] * rsqrtf(var + 1e-5f);
    sh = beta[c] - mu * sc;
}

// BN1 apply + relu -> bf16 planes (feeds GEMM2)
__global__ void k_bnapplyS(const float* __restrict__ X,
                           const float* __restrict__ gamma, const float* __restrict__ beta,
                           const float* __restrict__ sum, const float* __restrict__ sq) {
    int idx = blockIdx.x * 256 + threadIdx.x;
    int c = idx & (2*EMB - 1);
    float sc, sh;
    bn_coef(sum, sq, gamma, beta, c, sc, sh);
    float v = fmaxf(X[idx] * sc + sh, 0.f);
    splitw(v, g_th, g_tl, idx);
}

// BN2 apply -> fp32 (h for next layer, or final output)
__global__ void k_bnapply(const float* __restrict__ X, float* __restrict__ O,
                          const float* __restrict__ gamma, const float* __restrict__ beta,
                          const float* __restrict__ sum, const float* __restrict__ sq,
                          int act) {
    int idx = blockIdx.x * 256 + threadIdx.x;
    int c = idx & 255;
    float sc, sh;
    bn_coef(sum, sq, gamma, beta, c, sc, sh);
    float v = X[idx] * sc + sh;
    if (act) v = fmaxf(v, 0.f);
    O[idx] = v;
}

// vt[b] = sum_nodes hin + vn[b]
__global__ void k_vt(const float* __restrict__ vnp, int vnstride) {
    int b = blockIdx.x, c = threadIdx.x;
    const float* base = g_hin + (size_t)b*NPG*EMB + c;
    float s = 0.f;
    #pragma unroll 4
    for (int r = 0; r < NPG; r++) s += base[(size_t)r*EMB];
    splitw(s + vnp[b*vnstride + c], g_vth, g_vtl, b*EMB + c);
}

// ------------------------------ host orchestration --------------------------
extern "C" void kernel_launch(void* const* d_in, const int* in_sizes, int n_in,
                              void* d_out, int out_size) {
    const int ab = n_in - 19;
    const int*   atom_idx = (const int*)  d_in[0];
    const int*   lei      = (const int*)  d_in[1];
    const int*   eai      = (const int*)  d_in[2];
    const float* atom_emb = (const float*)d_in[ab + 0];
    const float* bemb_h   = (const float*)d_in[ab + 1];
    const float* elin_w   = (const float*)d_in[ab + 2];
    const float* elin_b   = (const float*)d_in[ab + 3];
    const float* bemb_l   = (const float*)d_in[ab + 4];
    const float* gin_eps  = (const float*)d_in[ab + 5];
    const float* mlp_w1   = (const float*)d_in[ab + 6];
    const float* mlp_b1   = (const float*)d_in[ab + 7];
    const float* bn_g     = (const float*)d_in[ab + 8];
    const float* bn_b     = (const float*)d_in[ab + 9];
    const float* mlp_w2   = (const float*)d_in[ab + 10];
    const float* mlp_b2   = (const float*)d_in[ab + 11];
    const float* obn_g    = (const float*)d_in[ab + 12];
    const float* obn_b    = (const float*)d_in[ab + 13];
    const float* vn_emb   = (const float*)d_in[ab + 14];
    const float* vn_w1    = (const float*)d_in[ab + 15];
    const float* vn_b1    = (const float*)d_in[ab + 16];
    const float* vn_w2    = (const float*)d_in[ab + 17];
    const float* vn_b2    = (const float*)d_in[ab + 18];
    float* out = (float*)d_out;

    static int smem_set = 0;
    if (!smem_set) {
        cudaFuncSetAttribute(k_mma, cudaFuncAttributeMaxDynamicSharedMemorySize, SMEM_BYTES);
        smem_set = 1;
    }

    float *p_t, *p_h2, *p_h, *p_vn, *p_sum, *p_sq;
    cudaGetSymbolAddress((void**)&p_t,  g_t);
    cudaGetSymbolAddress((void**)&p_h2, g_h2);
    cudaGetSymbolAddress((void**)&p_h,  g_h);
    cudaGetSymbolAddress((void**)&p_vn, g_vn);
    cudaGetSymbolAddress((void**)&p_sum, g_sum);
    cudaGetSymbolAddress((void**)&p_sq,  g_sq);
    bf16 *pAh, *pAl, *px1h, *px1l, *px2h, *px2l, *pzh, *pzl, *pth, *ptl;
    bf16 *pvth, *pvtl, *pvhh, *pvhl, *pw1h, *pw1l, *pw2h, *pw2l, *pu1h, *pu1l, *pu2h, *pu2l;
    cudaGetSymbolAddress((void**)&pAh,  g_Ahp);
    cudaGetSymbolAddress((void**)&pAl,  g_Alp);
    cudaGetSymbolAddress((void**)&px1h, g_x1h);
    cudaGetSymbolAddress((void**)&px1l, g_x1l);
    cudaGetSymbolAddress((void**)&px2h, g_x2h);
    cudaGetSymbolAddress((void**)&px2l, g_x2l);
    cudaGetSymbolAddress((void**)&pzh,  g_zh);
    cudaGetSymbolAddress((void**)&pzl,  g_zl);
    cudaGetSymbolAddress((void**)&pth,  g_th);
    cudaGetSymbolAddress((void**)&ptl,  g_tl);
    cudaGetSymbolAddress((void**)&pvth, g_vth);
    cudaGetSymbolAddress((void**)&pvtl, g_vtl);
    cudaGetSymbolAddress((void**)&pvhh, g_vhh);
    cudaGetSymbolAddress((void**)&pvhl, g_vhl);
    cudaGetSymbolAddress((void**)&pw1h, g_w1h);
    cudaGetSymbolAddress((void**)&pw1l, g_w1l);
    cudaGetSymbolAddress((void**)&pw2h, g_w2h);
    cudaGetSymbolAddress((void**)&pw2l, g_w2l);
    cudaGetSymbolAddress((void**)&pu1h, g_u1h);
    cudaGetSymbolAddress((void**)&pu1l, g_u1l);
    cudaGetSymbolAddress((void**)&pu2h, g_u2h);
    cudaGetSymbolAddress((void**)&pu2l, g_u2l);

    const int NE = NTOT*EMB/256;
    const int W  = EMB*2*EMB;

    // ---- setup ----
    k_zero<<<NTOT/256, 256>>>();
    k_ewt<<<1, 512>>>(bemb_h, elin_w, elin_b);
    k_scatter<<<ETOT/256, 256>>>(lei, eai);
    k_adjprep<<<4*BG, 256>>>();
    k_scan<<<BG, 256>>>();          // finalizes g_cs (rsqrt) + CSR ptrs
    k_adjnorm<<<(int)((size_t)BG*NPG*NPG/256), 256>>>();
    k_csrfill<<<ETOT/256, 256>>>(lei, eai);
    k_gather<<<NE, 256>>>(atom_idx, atom_emb);
    k_split<<<NL*W/256, 256>>>(mlp_w1, pw1h, pw1l, NL*W);
    k_split<<<NL*W/256, 256>>>(mlp_w2, pw2h, pw2l, NL*W);
    k_split<<<(NL-1)*W/256, 256>>>(vn_w1, pu1h, pu1l, (NL-1)*W);
    k_split<<<(NL-1)*W/256, 256>>>(vn_w2, pu2h, pu2l, (NL-1)*W);

    // ---- propagation: g_h accumulates f + Af + A^2 f + A^3 f ----
    dim3 pg(EMB/BN, NPG/BM, BG);
    long sAdj = (long)NPG*NPG, sX = (long)NPG*EMB;
    k_mma<<<pg, 256, SMEM_BYTES>>>(pAh, pAl, px1h, px1l, nullptr,
                                   nullptr, px2h, px2l, p_h, 0, NPG, EMB, NPG, sAdj, sX, sX);
    k_mma<<<pg, 256, SMEM_BYTES>>>(pAh, pAl, px2h, px2l, nullptr,
                                   nullptr, px1h, px1l, p_h, 0, NPG, EMB, NPG, sAdj, sX, sX);
    k_mma<<<pg, 256, SMEM_BYTES>>>(pAh, pAl, px1h, px1l, nullptr,
                                   nullptr, px2h, px2l, p_h, 0, NPG, EMB, NPG, sAdj, sX, sX);

    // ---- GIN + virtual-node stack ----
    const float* vnp = vn_emb;
    int vnstride = 0;

    for (int l = 0; l < NL; l++) {
        float hscale = (l == 0) ? 0.25f : 1.0f;
        k_agg<<<NTOT, 256>>>(bemb_l + (size_t)l*16*EMB, gin_eps + l, vnp, vnstride, hscale);

        float* s1 = p_sum + (l*2+0)*512;  float* q1 = p_sq + (l*2+0)*512;
        float* s2 = p_sum + (l*2+1)*512;  float* q2 = p_sq + (l*2+1)*512;

        // GEMM1: t = z @ w1 + b1  [N, 512] fp32
        k_mma<<<dim3(2*EMB/BN, NTOT/BM, 1), 256, SMEM_BYTES>>>(
            pzh, pzl, pw1h + (size_t)l*W, pw1l + (size_t)l*W, mlp_b1 + (size_t)l*2*EMB,
            p_t, nullptr, nullptr, nullptr, 0, NTOT, 2*EMB, EMB, 0, 0, 0);
        k_bnstats<<<NTOT/64, 256>>>(p_t, 2*EMB, s1, q1);
        k_bnapplyS<<<NTOT*2*EMB/256, 256>>>(p_t, bn_g + (size_t)l*2*EMB,
                                            bn_b + (size_t)l*2*EMB, s1, q1);

        // GEMM2: h2 = t' @ w2 + b2  [N, 256] fp32
        k_mma<<<dim3(EMB/BN, NTOT/BM, 1), 256, SMEM_BYTES>>>(
            pth, ptl, pw2h + (size_t)l*W, pw2l + (size_t)l*W, mlp_b2 + (size_t)l*EMB,
            p_h2, nullptr, nullptr, nullptr, 0, NTOT, EMB, 2*EMB, 0, 0, 0);
        k_bnstats<<<NTOT/64, 256>>>(p_h2, EMB, s2, q2);
        if (l < NL - 1)
            k_bnapply<<<NE, 256>>>(p_h2, p_h, obn_g + (size_t)l*EMB,
                                   obn_b + (size_t)l*EMB, s2, q2, 1);
        else
            k_bnapply<<<NE, 256>>>(p_h2, out, obn_g + (size_t)l*EMB,
                                   obn_b + (size_t)l*EMB, s2, q2, 0);

        // virtual node update
        if (l < NL - 1) {
            k_vt<<<BG, 256>>>(vnp, vnstride);
            k_mma<<<dim3(2*EMB/BN, 1, 1), 256, SMEM_BYTES>>>(
                pvth, pvtl, pu1h + (size_t)l*W, pu1l + (size_t)l*W, vn_b1 + (size_t)l*2*EMB,
                nullptr, pvhh, pvhl, nullptr, 1, 128, 2*EMB, EMB, 0, 0, 0);
            k_mma<<<dim3(EMB/BN, 1, 1), 256, SMEM_BYTES>>>(
                pvhh, pvhl, pu2h + (size_t)l*W, pu2l + (size_t)l*W, vn_b2 + (size_t)l*EMB,
                p_vn, nullptr, nullptr, nullptr, 1, 128, EMB, 2*EMB, 0, 0, 0);
        }

        vnp = p_vn; vnstride = EMB;
    }

    (void)in_sizes; (void)out_size;
}

// round 17
// speedup vs baseline: 1.2051x; 1.0428x over previous
#include <cuda_runtime.h>
#include <cuda_bf16.h>
#include <math.h>

#define BG   128
#define NPG  256
#define EPG  2048
#define EMB  256
#define NL   5
#define NTOT (BG*NPG)     // 32768 nodes
#define ETOT (BG*EPG)     // 262144 edges

typedef unsigned long long ull;
typedef __nv_bfloat16 bf16;

// ------------------------------ scratch (device globals; no allocs) ---------
// 32-bit packed adjacency keys: ((edge_idx+1)<<4) | bond_type.
// INVARIANT: all-zero at entry (zero-init at load; k_adjnorm restores zeros).
__device__ unsigned g_pk[(size_t)BG*NPG*NPG];
__device__ float g_cs [BG*NPG];      // raw col sums -> rsqrt'd by k_scan
__device__ float g_rs [BG*NPG];      // rsqrt(row sums)
__device__ float g_h  [NTOT*EMB];
__device__ float g_hin[NTOT*EMB];
__device__ float g_t  [NTOT*2*EMB];
__device__ float g_h2 [NTOT*EMB];
__device__ float g_vn [BG*EMB];
__device__ float g_vtr[BG*EMB];      // raw vt accumulator; INVARIANT: zero at entry
__device__ float g_ewt[16];
__device__ int   g_deg[NTOT];
__device__ int   g_ptr[NTOT];
__device__ int   g_cur[NTOT];
__device__ int   g_csrc[ETOT];
__device__ int   g_cea [ETOT];
// per-(layer,stage) BN stats: slot = l*2+stage, 512 floats per slot
__device__ float g_sum[NL*2*512];
__device__ float g_sq [NL*2*512];

// bf16 hi/lo planes (GEMM operands)
__device__ __align__(16) bf16 g_Ahp[(size_t)BG*NPG*NPG], g_Alp[(size_t)BG*NPG*NPG];
__device__ __align__(16) bf16 g_x1h[NTOT*EMB], g_x1l[NTOT*EMB];
__device__ __align__(16) bf16 g_x2h[NTOT*EMB], g_x2l[NTOT*EMB];
__device__ __align__(16) bf16 g_zh [NTOT*EMB], g_zl [NTOT*EMB];
__device__ __align__(16) bf16 g_th [NTOT*2*EMB], g_tl [NTOT*2*EMB];
__device__ __align__(16) bf16 g_vth[BG*EMB],   g_vtl[BG*EMB];
__device__ __align__(16) bf16 g_vhh[BG*2*EMB], g_vhl[BG*2*EMB];
__device__ __align__(16) bf16 g_w1h[NL*EMB*2*EMB],  g_w1l[NL*EMB*2*EMB];
__device__ __align__(16) bf16 g_w2h[NL*2*EMB*EMB],  g_w2l[NL*2*EMB*EMB];
__device__ __align__(16) bf16 g_u1h[(NL-1)*EMB*2*EMB], g_u1l[(NL-1)*EMB*2*EMB];
__device__ __align__(16) bf16 g_u2h[(NL-1)*2*EMB*EMB], g_u2l[(NL-1)*2*EMB*EMB];

__device__ __forceinline__ void splitw(float v, bf16* __restrict__ h,
                                       bf16* __restrict__ l, size_t i) {
    bf16 hv = __float2bfloat16(v);
    h[i] = hv;
    l[i] = __float2bfloat16(v - __bfloat162float(hv));
}

// ------------------------------ setup kernels -------------------------------
__global__ void k_zero() {
    int i = blockIdx.x * 256 + threadIdx.x;
    if (i < NTOT) { g_deg[i] = 0; g_cs[i] = 0.f; }
    if (i < NL*2*512) { g_sum[i] = 0.f; g_sq[i] = 0.f; }
}

__global__ void k_ewt(const float* __restrict__ bh, const float* __restrict__ w,
                      const float* __restrict__ b) {
    int warp = threadIdx.x >> 5, lane = threadIdx.x & 31;
    if (warp < 16) {
        float v = bh[warp*64 + lane] * w[lane] + bh[warp*64 + 32 + lane] * w[32 + lane];
        #pragma unroll
        for (int o = 16; o; o >>= 1) v += __shfl_down_sync(0xffffffffu, v, o);
        if (lane == 0) g_ewt[warp] = 1.f / (1.f + expf(-(v + b[0])));
    }
}

__global__ void k_scatter(const int* __restrict__ lei, const int* __restrict__ eai) {
    int idx = blockIdx.x * 256 + threadIdx.x;
    if (idx >= ETOT) return;
    int b = idx / EPG, k = idx - b * EPG;
    int s = lei[(size_t)b*2*EPG + k];
    int d = lei[(size_t)b*2*EPG + EPG + k];
    int t = eai[idx];
    unsigned key = ((unsigned)(k + 1) << 4) | (unsigned)t;
    atomicMax(&g_pk[(size_t)b*NPG*NPG + (size_t)s*NPG + d], key);
    atomicAdd(&g_deg[b*NPG + d], 1);
}

// per-graph row/col sums of (adj + I); 4 blocks per graph (64 rows each)
__global__ void k_adjprep() {
    int blk = blockIdx.x;
    int g = blk >> 2, q = blk & 3;
    int tid = threadIdx.x, lane = tid & 31, warp = tid >> 5;
    __shared__ float s_cs[NPG];
    for (int i = tid; i < NPG; i += 256) s_cs[i] = 0.f;
    __syncthreads();
    const unsigned* P = g_pk + (size_t)g*NPG*NPG;
    int r0 = q * 64;
    float csl[8] = {};
    for (int rb = 0; rb < 64; rb += 8) {
        int r = r0 + rb + warp;
        float rsum = 0.f;
        #pragma unroll
        for (int k = 0; k < 8; k++) {
            int c = lane + k*32;
            unsigned p = P[(size_t)r*NPG + c];
            float v = p ? g_ewt[p & 15u] : 0.f;
            if (r == c) v += 1.f;
            rsum += v;
            csl[k] += v;
        }
        #pragma unroll
        for (int o = 16; o; o >>= 1) rsum += __shfl_down_sync(0xffffffffu, rsum, o);
        if (lane == 0) g_rs[g*NPG + r] = rsqrtf(rsum);
    }
    #pragma unroll
    for (int k = 0; k < 8; k++) atomicAdd(&s_cs[lane + k*32], csl[k]);
    __syncthreads();
    for (int i = tid; i < NPG; i += 256)
        atomicAdd(&g_cs[g*NPG + i], s_cs[i]);
}

// degree scan -> CSR ptrs; ALSO finalizes g_cs: raw colsum -> rsqrt
__global__ void k_scan() {
    int g = blockIdx.x, tid = threadIdx.x;
    g_cs[g*NPG + tid] = rsqrtf(g_cs[g*NPG + tid]);
    __shared__ int s[NPG];
    int d = g_deg[g*NPG + tid];
    s[tid] = d;
    __syncthreads();
    for (int off = 1; off < NPG; off <<= 1) {
        int v = (tid >= off) ? s[tid - off] : 0;
        __syncthreads();
        s[tid] += v;
        __syncthreads();
    }
    int excl = s[tid] - d;
    g_ptr[g*NPG + tid] = g*EPG + excl;
    g_cur[g*NPG + tid] = g*EPG + excl;
}

// normalize + split to bf16 planes; restores the zero-pack invariant
__global__ void k_adjnorm() {
    size_t idx = (size_t)blockIdx.x * 256 + threadIdx.x;
    int g = (int)(idx >> 16);
    int r = (int)((idx >> 8) & 255);
    int c = (int)(idx & 255);
    unsigned p = g_pk[idx];
    float v = p ? g_ewt[p & 15u] : 0.f;
    if (p) g_pk[idx] = 0u;
    if (r == c) v += 1.f;
    v *= g_cs[g*NPG + r] * g_rs[g*NPG + c];
    splitw(v, g_Ahp, g_Alp, idx);
}

__global__ void k_csrfill(const int* __restrict__ lei, const int* __restrict__ eai) {
    int idx = blockIdx.x * 256 + threadIdx.x;
    if (idx >= ETOT) return;
    int b = idx / EPG, k = idx - b * EPG;
    int s = lei[(size_t)b*2*EPG + k];
    int d = lei[(size_t)b*2*EPG + EPG + k];
    int pos = atomicAdd(&g_cur[b*NPG + d], 1);
    g_csrc[pos] = b*NPG + s;
    g_cea [pos] = eai[idx];
}

__global__ void k_gather(const int* __restrict__ aidx, const float* __restrict__ aemb) {
    int idx = blockIdx.x * 256 + threadIdx.x;
    int n = idx >> 8, c = idx & 255;
    float v = aemb[aidx[n]*EMB + c];
    g_h[idx] = v;
    splitw(v, g_x1h, g_x1l, idx);
}

__global__ void k_split(const float* __restrict__ w, bf16* __restrict__ h,
                        bf16* __restrict__ l, int n) {
    int i = blockIdx.x * 256 + threadIdx.x;
    if (i < n) splitw(w[i], h, l, i);
}

// ------------------------------ pipelined bf16x3 tensor GEMM ----------------
#define BM 128
#define BN 64
#define APAD 40
#define BPAD 72
#define ASEG (128*APAD)
#define BSEG (32*BPAD)
#define BBASE (6*ASEG)
#define SMEM_BYTES ((6*ASEG + 6*BSEG)*2)   // 89088

__device__ __forceinline__ void cpa16(unsigned s, const void* g) {
    asm volatile("cp.async.cg.shared.global [%0], [%1], 16;" :: "r"(s), "l"(g));
}
#define LDSM4(r0,r1,r2,r3,a)                                                   \
    asm volatile("ldmatrix.sync.aligned.m8n8.x4.shared.b16 {%0,%1,%2,%3}, [%4];" \
        : "=r"(r0),"=r"(r1),"=r"(r2),"=r"(r3) : "r"(a))
#define LDSM4T(r0,r1,r2,r3,a)                                                  \
    asm volatile("ldmatrix.sync.aligned.m8n8.x4.trans.shared.b16 {%0,%1,%2,%3}, [%4];" \
        : "=r"(r0),"=r"(r1),"=r"(r2),"=r"(r3) : "r"(a))
#define MMA_BF16(c, a, b)                                                     \
    asm volatile(                                                             \
        "mma.sync.aligned.m16n8k16.row.col.f32.bf16.bf16.f32 "                \
        "{%0,%1,%2,%3}, {%4,%5,%6,%7}, {%8,%9}, {%0,%1,%2,%3};\n"             \
        : "+f"((c)[0]), "+f"((c)[1]), "+f"((c)[2]), "+f"((c)[3])              \
        : "r"((a)[0]), "r"((a)[1]), "r"((a)[2]), "r"((a)[3]),                 \
          "r"((b)[0]), "r"((b)[1]))

__global__ void __launch_bounds__(256, 2)
k_mma(const bf16* __restrict__ Ah, const bf16* __restrict__ Al,
      const bf16* __restrict__ Bh, const bf16* __restrict__ Bl,
      const float* __restrict__ bias,
      float* __restrict__ Cf, bf16* __restrict__ Chi, bf16* __restrict__ Clo,
      float* __restrict__ Y, int relu,
      int M, int N, int K, long sA, long sB, long sC) {
    extern __shared__ bf16 smbuf[];
    Ah += (size_t)blockIdx.z * sA;  Al += (size_t)blockIdx.z * sA;
    Bh += (size_t)blockIdx.z * sB;  Bl += (size_t)blockIdx.z * sB;
    if (Cf)  Cf  += (size_t)blockIdx.z * sC;
    if (Chi) { Chi += (size_t)blockIdx.z * sC; Clo += (size_t)blockIdx.z * sC; }
    if (Y)   Y   += (size_t)blockIdx.z * sC;

    unsigned sb = (unsigned)__cvta_generic_to_shared(smbuf);
    int tid = threadIdx.x, lane = tid & 31, warp = tid >> 5;
    int wm = warp >> 1, wn = warp & 1;
    int bm = blockIdx.y * BM, bn = blockIdx.x * BN;

    int ar = tid >> 2, ac = (tid & 3) * 8;
    int br = tid >> 3, bc = (tid & 7) * 8;
    int lr = lane & 15, lc = (lane >> 4) * 8;

    float acc[2][4][4];
    #pragma unroll
    for (int i = 0; i < 2; i++)
        #pragma unroll
        for (int j = 0; j < 4; j++)
            #pragma unroll
            for (int r = 0; r < 4; r++) acc[i][j][r] = 0.f;

    int niter = K / 32;

#define ISSUE(buf, kk) {                                                         \
    unsigned a0 = sb + (unsigned)(((buf)*2+0)*ASEG)*2;                            \
    unsigned a1 = sb + (unsigned)(((buf)*2+1)*ASEG)*2;                            \
    unsigned b0 = sb + (unsigned)((BBASE + ((buf)*2+0)*BSEG))*2;                  \
    unsigned b1 = sb + (unsigned)((BBASE + ((buf)*2+1)*BSEG))*2;                  \
    cpa16(a0 + (ar*APAD + ac)*2,      Ah + (size_t)(bm + ar)*K + (kk) + ac);      \
    cpa16(a0 + ((ar+64)*APAD + ac)*2, Ah + (size_t)(bm + ar + 64)*K + (kk) + ac); \
    cpa16(a1 + (ar*APAD + ac)*2,      Al + (size_t)(bm + ar)*K + (kk) + ac);      \
    cpa16(a1 + ((ar+64)*APAD + ac)*2, Al + (size_t)(bm + ar + 64)*K + (kk) + ac); \
    cpa16(b0 + (br*BPAD + bc)*2,      Bh + (size_t)((kk) + br)*N + bn + bc);      \
    cpa16(b1 + (br*BPAD + bc)*2,      Bl + (size_t)((kk) + br)*N + bn + bc);      \
}

    ISSUE(0, 0);
    asm volatile("cp.async.commit_group;");
    ISSUE(1, 32);
    asm volatile("cp.async.commit_group;");

    int cbuf = 0, ibuf = 2;
    for (int it = 0; it < niter; it++) {
        asm volatile("cp.async.wait_group 1;");
        __syncthreads();
        if (it + 2 < niter) { int kk = (it + 2) * 32; ISSUE(ibuf, kk); }
        asm volatile("cp.async.commit_group;");

        unsigned aH = sb + (unsigned)((cbuf*2+0)*ASEG)*2;
        unsigned aL = sb + (unsigned)((cbuf*2+1)*ASEG)*2;
        unsigned bH = sb + (unsigned)((BBASE + (cbuf*2+0)*BSEG))*2;
        unsigned bL = sb + (unsigned)((BBASE + (cbuf*2+1)*BSEG))*2;

        #pragma unroll
        for (int ks = 0; ks < 2; ks++) {
            unsigned ah[2][4], al[2][4], bh[4][2], bl[4][2];
            #pragma unroll
            for (int mf = 0; mf < 2; mf++) {
                unsigned off = (unsigned)(((wm*32 + mf*16 + lr)*APAD + ks*16 + lc)*2);
                LDSM4(ah[mf][0], ah[mf][1], ah[mf][2], ah[mf][3], aH + off);
                LDSM4(al[mf][0], al[mf][1], al[mf][2], al[mf][3], aL + off);
            }
            #pragma unroll
            for (int p = 0; p < 2; p++) {
                unsigned off = (unsigned)(((ks*16 + lr)*BPAD + wn*32 + p*16 + lc)*2);
                unsigned r0, r1, r2, r3;
                LDSM4T(r0, r1, r2, r3, bH + off);
                bh[2*p][0] = r0; bh[2*p][1] = r1; bh[2*p+1][0] = r2; bh[2*p+1][1] = r3;
                LDSM4T(r0, r1, r2, r3, bL + off);
                bl[2*p][0] = r0; bl[2*p][1] = r1; bl[2*p+1][0] = r2; bl[2*p+1][1] = r3;
            }
            #pragma unroll
            for (int mf = 0; mf < 2; mf++)
                #pragma unroll
                for (int nf = 0; nf < 4; nf++) {
                    float* c = acc[mf][nf];
                    MMA_BF16(c, ah[mf], bl[nf]);
                    MMA_BF16(c, al[mf], bh[nf]);
                    MMA_BF16(c, ah[mf], bh[nf]);
                }
        }
        cbuf = (cbuf == 2) ? 0 : cbuf + 1;
        ibuf = (ibuf == 2) ? 0 : ibuf + 1;
    }

    // ---- epilogue ----
    int gid = lane >> 2, tig = lane & 3;
    #pragma unroll
    for (int mf = 0; mf < 2; mf++) {
        #pragma unroll
        for (int nf = 0; nf < 4; nf++) {
            int r0 = bm + wm*32 + mf*16 + gid;
            int c0 = bn + wn*32 + nf*8 + 2*tig;
            float b0 = 0.f, b1 = 0.f;
            if (bias) { b0 = bias[c0]; b1 = bias[c0+1]; }
            float* c = acc[mf][nf];
            #pragma unroll
            for (int half = 0; half < 2; half++) {
                int r = r0 + half*8;
                float v0 = c[half*2+0] + b0, v1 = c[half*2+1] + b1;
                if (relu) { v0 = fmaxf(v0, 0.f); v1 = fmaxf(v1, 0.f); }
                if (Cf)
                    *reinterpret_cast<float2*>(Cf + (size_t)r*N + c0) = make_float2(v0, v1);
                if (Chi) {
                    bf16 h0 = __float2bfloat16(v0), h1 = __float2bfloat16(v1);
                    *reinterpret_cast<__nv_bfloat162*>(Chi + (size_t)r*N + c0) =
                        __halves2bfloat162(h0, h1);
                    bf16 l0 = __float2bfloat16(v0 - __bfloat162float(h0));
                    bf16 l1 = __float2bfloat16(v1 - __bfloat162float(h1));
                    *reinterpret_cast<__nv_bfloat162*>(Clo + (size_t)r*N + c0) =
                        __halves2bfloat162(l0, l1);
                }
                if (Y) {
                    float2* y = reinterpret_cast<float2*>(Y + (size_t)r*N + c0);
                    float2 yo = *y;
                    yo.x += v0; yo.y += v1;
                    *y = yo;
                }
            }
        }
    }
#undef ISSUE
}

// ------------------------------ fused GIN aggregate --------------------------
__global__ void k_agg(const float* __restrict__ eembL, const float* __restrict__ epsp,
                      const float* __restrict__ vnp, int vnstride, float hscale) {
    int n = blockIdx.x, c = threadIdx.x;
    int b = n >> 8;
    float vnv = vnp[b*vnstride + c];
    int start = g_ptr[n], deg = g_deg[n];
    float own = g_h[(size_t)n*EMB + c] * hscale + vnv;
    g_hin[(size_t)n*EMB + c] = own;
    float val = 0.f;
    for (int k = 0; k < deg; k++) {
        int s = g_csrc[start + k];
        int t = g_cea [start + k];
        float m = g_h[(size_t)s*EMB + c] * hscale + vnv + eembL[t*EMB + c];
        val += fmaxf(m, 0.f);
    }
    float z = (1.f + *epsp) * own + val;
    splitw(z, g_zh, g_zl, (size_t)n*EMB + c);
}

// ------------------------------ batchnorm -----------------------------------
// 64 rows per block (512 blocks) for latency hiding
__global__ void k_bnstats(const float* __restrict__ X, int C,
                          float* __restrict__ sum, float* __restrict__ sq) {
    int r0 = blockIdx.x * 64;
    for (int c = threadIdx.x; c < C; c += 256) {
        float s = 0.f, q = 0.f;
        for (int r = 0; r < 64; r++) {
            float v = X[(size_t)(r0 + r)*C + c];
            s += v; q += v * v;
        }
        atomicAdd(&sum[c], s);
        atomicAdd(&sq[c], q);
    }
}

__device__ __forceinline__ void bn_coef(const float* __restrict__ sum,
                                        const float* __restrict__ sq,
                                        const float* __restrict__ gamma,
                                        const float* __restrict__ beta,
                                        int c, float& sc, float& sh) {
    float mu  = sum[c] * (1.f / NTOT);
    float var = sq[c] * (1.f / NTOT) - mu * mu;
    sc = gamma[c] * rsqrtf(var + 1e-5f);
    sh = beta[c] - mu * sc;
}

// BN1 apply + relu -> bf16 planes (feeds GEMM2)
__global__ void k_bnapplyS(const float* __restrict__ X,
                           const float* __restrict__ gamma, const float* __restrict__ beta,
                           const float* __restrict__ sum, const float* __restrict__ sq) {
    int idx = blockIdx.x * 256 + threadIdx.x;
    int c = idx & (2*EMB - 1);
    float sc, sh;
    bn_coef(sum, sq, gamma, beta, c, sc, sh);
    float v = fmaxf(X[idx] * sc + sh, 0.f);
    splitw(v, g_th, g_tl, idx);
}

// BN2 apply -> fp32 (h for next layer, or final output)
__global__ void k_bnapply(const float* __restrict__ X, float* __restrict__ O,
                          const float* __restrict__ gamma, const float* __restrict__ beta,
                          const float* __restrict__ sum, const float* __restrict__ sq,
                          int act) {
    int idx = blockIdx.x * 256 + threadIdx.x;
    int c = idx & 255;
    float sc, sh;
    bn_coef(sum, sq, gamma, beta, c, sc, sh);
    float v = X[idx] * sc + sh;
    if (act) v = fmaxf(v, 0.f);
    O[idx] = v;
}

// partial vt sums: 4 blocks per graph, 64 rows each -> atomicAdd into g_vtr
__global__ void k_vt() {
    int blk = blockIdx.x;
    int b = blk >> 2, q = blk & 3;
    int c = threadIdx.x;
    const float* base = g_hin + (size_t)b*NPG*EMB + (size_t)q*64*EMB + c;
    float s = 0.f;
    #pragma unroll 4
    for (int r = 0; r < 64; r++) s += base[(size_t)r*EMB];
    atomicAdd(&g_vtr[b*EMB + c], s);
}

// finalize vt: add vn, split to planes, restore g_vtr zero invariant
__global__ void k_vtfin(const float* __restrict__ vnp, int vnstride) {
    int b = blockIdx.x, c = threadIdx.x;
    float s = g_vtr[b*EMB + c] + vnp[b*vnstride + c];
    g_vtr[b*EMB + c] = 0.f;
    splitw(s, g_vth, g_vtl, b*EMB + c);
}

// ------------------------------ host orchestration --------------------------
extern "C" void kernel_launch(void* const* d_in, const int* in_sizes, int n_in,
                              void* d_out, int out_size) {
    const int ab = n_in - 19;
    const int*   atom_idx = (const int*)  d_in[0];
    const int*   lei      = (const int*)  d_in[1];
    const int*   eai      = (const int*)  d_in[2];
    const float* atom_emb = (const float*)d_in[ab + 0];
    const float* bemb_h   = (const float*)d_in[ab + 1];
    const float* elin_w   = (const float*)d_in[ab + 2];
    const float* elin_b   = (const float*)d_in[ab + 3];
    const float* bemb_l   = (const float*)d_in[ab + 4];
    const float* gin_eps  = (const float*)d_in[ab + 5];
    const float* mlp_w1   = (const float*)d_in[ab + 6];
    const float* mlp_b1   = (const float*)d_in[ab + 7];
    const float* bn_g     = (const float*)d_in[ab + 8];
    const float* bn_b     = (const float*)d_in[ab + 9];
    const float* mlp_w2   = (const float*)d_in[ab + 10];
    const float* mlp_b2   = (const float*)d_in[ab + 11];
    const float* obn_g    = (const float*)d_in[ab + 12];
    const float* obn_b    = (const float*)d_in[ab + 13];
    const float* vn_emb   = (const float*)d_in[ab + 14];
    const float* vn_w1    = (const float*)d_in[ab + 15];
    const float* vn_b1    = (const float*)d_in[ab + 16];
    const float* vn_w2    = (const float*)d_in[ab + 17];
    const float* vn_b2    = (const float*)d_in[ab + 18];
    float* out = (float*)d_out;

    static int smem_set = 0;
    if (!smem_set) {
        cudaFuncSetAttribute(k_mma, cudaFuncAttributeMaxDynamicSharedMemorySize, SMEM_BYTES);
        smem_set = 1;
    }

    float *p_t, *p_h2, *p_h, *p_vn, *p_sum, *p_sq;
    cudaGetSymbolAddress((void**)&p_t,  g_t);
    cudaGetSymbolAddress((void**)&p_h2, g_h2);
    cudaGetSymbolAddress((void**)&p_h,  g_h);
    cudaGetSymbolAddress((void**)&p_vn, g_vn);
    cudaGetSymbolAddress((void**)&p_sum, g_sum);
    cudaGetSymbolAddress((void**)&p_sq,  g_sq);
    bf16 *pAh, *pAl, *px1h, *px1l, *px2h, *px2l, *pzh, *pzl, *pth, *ptl;
    bf16 *pvth, *pvtl, *pvhh, *pvhl, *pw1h, *pw1l, *pw2h, *pw2l, *pu1h, *pu1l, *pu2h, *pu2l;
    cudaGetSymbolAddress((void**)&pAh,  g_Ahp);
    cudaGetSymbolAddress((void**)&pAl,  g_Alp);
    cudaGetSymbolAddress((void**)&px1h, g_x1h);
    cudaGetSymbolAddress((void**)&px1l, g_x1l);
    cudaGetSymbolAddress((void**)&px2h, g_x2h);
    cudaGetSymbolAddress((void**)&px2l, g_x2l);
    cudaGetSymbolAddress((void**)&pzh,  g_zh);
    cudaGetSymbolAddress((void**)&pzl,  g_zl);
    cudaGetSymbolAddress((void**)&pth,  g_th);
    cudaGetSymbolAddress((void**)&ptl,  g_tl);
    cudaGetSymbolAddress((void**)&pvth, g_vth);
    cudaGetSymbolAddress((void**)&pvtl, g_vtl);
    cudaGetSymbolAddress((void**)&pvhh, g_vhh);
    cudaGetSymbolAddress((void**)&pvhl, g_vhl);
    cudaGetSymbolAddress((void**)&pw1h, g_w1h);
    cudaGetSymbolAddress((void**)&pw1l, g_w1l);
    cudaGetSymbolAddress((void**)&pw2h, g_w2h);
    cudaGetSymbolAddress((void**)&pw2l, g_w2l);
    cudaGetSymbolAddress((void**)&pu1h, g_u1h);
    cudaGetSymbolAddress((void**)&pu1l, g_u1l);
    cudaGetSymbolAddress((void**)&pu2h, g_u2h);
    cudaGetSymbolAddress((void**)&pu2l, g_u2l);

    const int NE = NTOT*EMB/256;
    const int W  = EMB*2*EMB;

    // ---- setup ----
    k_zero<<<NTOT/256, 256>>>();
    k_ewt<<<1, 512>>>(bemb_h, elin_w, elin_b);
    k_scatter<<<ETOT/256, 256>>>(lei, eai);
    k_adjprep<<<4*BG, 256>>>();
    k_scan<<<BG, 256>>>();
    k_adjnorm<<<(int)((size_t)BG*NPG*NPG/256), 256>>>();
    k_csrfill<<<ETOT/256, 256>>>(lei, eai);
    k_gather<<<NE, 256>>>(atom_idx, atom_emb);
    k_split<<<NL*W/256, 256>>>(mlp_w1, pw1h, pw1l, NL*W);
    k_split<<<NL*W/256, 256>>>(mlp_w2, pw2h, pw2l, NL*W);
    k_split<<<(NL-1)*W/256, 256>>>(vn_w1, pu1h, pu1l, (NL-1)*W);
    k_split<<<(NL-1)*W/256, 256>>>(vn_w2, pu2h, pu2l, (NL-1)*W);

    // ---- propagation: g_h accumulates f + Af + A^2 f + A^3 f ----
    dim3 pg(EMB/BN, NPG/BM, BG);
    long sAdj = (long)NPG*NPG, sX = (long)NPG*EMB;
    k_mma<<<pg, 256, SMEM_BYTES>>>(pAh, pAl, px1h, px1l, nullptr,
                                   nullptr, px2h, px2l, p_h, 0, NPG, EMB, NPG, sAdj, sX, sX);
    k_mma<<<pg, 256, SMEM_BYTES>>>(pAh, pAl, px2h, px2l, nullptr,
                                   nullptr, px1h, px1l, p_h, 0, NPG, EMB, NPG, sAdj, sX, sX);
    k_mma<<<pg, 256, SMEM_BYTES>>>(pAh, pAl, px1h, px1l, nullptr,
                                   nullptr, px2h, px2l, p_h, 0, NPG, EMB, NPG, sAdj, sX, sX);

    // ---- GIN + virtual-node stack ----
    const float* vnp = vn_emb;
    int vnstride = 0;

    for (int l = 0; l < NL; l++) {
        float hscale = (l == 0) ? 0.25f : 1.0f;
        k_agg<<<NTOT, 256>>>(bemb_l + (size_t)l*16*EMB, gin_eps + l, vnp, vnstride, hscale);

        float* s1 = p_sum + (l*2+0)*512;  float* q1 = p_sq + (l*2+0)*512;
        float* s2 = p_sum + (l*2+1)*512;  float* q2 = p_sq + (l*2+1)*512;

        // GEMM1: t = z @ w1 + b1  [N, 512] fp32
        k_mma<<<dim3(2*EMB/BN, NTOT/BM, 1), 256, SMEM_BYTES>>>(
            pzh, pzl, pw1h + (size_t)l*W, pw1l + (size_t)l*W, mlp_b1 + (size_t)l*2*EMB,
            p_t, nullptr, nullptr, nullptr, 0, NTOT, 2*EMB, EMB, 0, 0, 0);
        k_bnstats<<<NTOT/64, 256>>>(p_t, 2*EMB, s1, q1);
        k_bnapplyS<<<NTOT*2*EMB/256, 256>>>(p_t, bn_g + (size_t)l*2*EMB,
                                            bn_b + (size_t)l*2*EMB, s1, q1);

        // GEMM2: h2 = t' @ w2 + b2  [N, 256] fp32
        k_mma<<<dim3(EMB/BN, NTOT/BM, 1), 256, SMEM_BYTES>>>(
            pth, ptl, pw2h + (size_t)l*W, pw2l + (size_t)l*W, mlp_b2 + (size_t)l*EMB,
            p_h2, nullptr, nullptr, nullptr, 0, NTOT, EMB, 2*EMB, 0, 0, 0);
        k_bnstats<<<NTOT/64, 256>>>(p_h2, EMB, s2, q2);
        if (l < NL - 1)
            k_bnapply<<<NE, 256>>>(p_h2, p_h, obn_g + (size_t)l*EMB,
                                   obn_b + (size_t)l*EMB, s2, q2, 1);
        else
            k_bnapply<<<NE, 256>>>(p_h2, out, obn_g + (size_t)l*EMB,
                                   obn_b + (size_t)l*EMB, s2, q2, 0);

        // virtual node update (parallel partial sums + finalize)
        if (l < NL - 1) {
            k_vt<<<4*BG, 256>>>();
            k_vtfin<<<BG, 256>>>(vnp, vnstride);
            k_mma<<<dim3(2*EMB/BN, 1, 1), 256, SMEM_BYTES>>>(
                pvth, pvtl, pu1h + (size_t)l*W, pu1l + (size_t)l*W, vn_b1 + (size_t)l*2*EMB,
                nullptr, pvhh, pvhl, nullptr, 1, 128, 2*EMB, EMB, 0, 0, 0);
            k_mma<<<dim3(EMB/BN, 1, 1), 256, SMEM_BYTES>>>(
                pvhh, pvhl, pu2h + (size_t)l*W, pu2l + (size_t)l*W, vn_b2 + (size_t)l*EMB,
                p_vn, nullptr, nullptr, nullptr, 1, 128, EMB, 2*EMB, 0, 0, 0);
        }

        vnp = p_vn; vnstride = EMB;
    }

    (void)in_sizes; (void)out_size;
}